// round 6
// baseline (speedup 1.0000x reference)
#include <cuda_runtime.h>

#define NPTS   8192
#define BATCH  8
#define S_ALL  512
#define K_ATTN 128
#define K_NONE 384
#define DF     64

// ---------------- scratch (static device arrays; no allocation) ----------------
__device__ float g_pts_t[BATCH * NPTS * DF];      // points transposed to [B][N][64]
__device__ float g_new_xyz[BATCH * S_ALL * 3];    // sampled (masked) coords [B][S][3]
__device__ float g_w0p[64 * 68];                  // w0 padded to [64][68]

// ---------------- tiny prep: pad w0 rows 67 -> 68 ----------------
__global__ void prep_w0_kernel(const float* __restrict__ w0) {
    int i = blockIdx.x * 256 + threadIdx.x;
    if (i < 64 * 68) {
        int r = i / 68, c = i % 68;
        g_w0p[i] = (c < 67) ? w0[r * 67 + c] : 0.0f;
    }
}

// ---------------- transpose points [B,64,N] -> [B,N,64] ----------------
__global__ void transpose_kernel(const float* __restrict__ points) {
    __shared__ float tile[32][33];
    int b  = blockIdx.z;
    int c0 = blockIdx.y * 32;
    int n0 = blockIdx.x * 32;
    int tx = threadIdx.x, ty = threadIdx.y;
    tile[ty][tx] = points[(b * DF + c0 + ty) * NPTS + n0 + tx];
    __syncthreads();
    g_pts_t[(b * NPTS + n0 + ty) * DF + c0 + tx] = tile[tx][ty];
}

// ---------------- FPS with origin-duplicate compression ----------------
__global__ __launch_bounds__(1024) void fps_kernel(
    const float* __restrict__ xyz, const float* __restrict__ attention,
    float* __restrict__ out)
{
    extern __shared__ float dsm[];
    float* sx  = dsm;                    // [8193]
    float* sy  = sx + 8193;
    float* sz  = sy + 8193;
    int*   sid = (int*)(sz + 8193);      // [8193]
    float* smd = (float*)(sid + 8193);   // [4097] overflow min-dist

    __shared__ unsigned sscan[32];
    __shared__ unsigned long long sred[2][32];
    __shared__ int srep;

    int bb = blockIdx.x;
    int b = bb >> 1;
    int branch = bb & 1;
    int K     = branch ? K_NONE : K_ATTN;
    int s_off = branch ? K_ATTN : 0;
    int t = threadIdx.x;
    int wid = t >> 5, lane = t & 31;

    const float* xb = xyz + (size_t)b * 3 * NPTS;
    const float* ab = attention + (size_t)b * NPTS;

    if (t == 0) srep = 0x7FFFFFFF;

    int n0 = t * 8;
    float X[8], Y[8], Z[8], W[8];
    {
        const float4* p = (const float4*)(xb + n0);
        float4 v0 = p[0], v1 = p[1];
        X[0]=v0.x; X[1]=v0.y; X[2]=v0.z; X[3]=v0.w; X[4]=v1.x; X[5]=v1.y; X[6]=v1.z; X[7]=v1.w;
        p = (const float4*)(xb + NPTS + n0);
        v0 = p[0]; v1 = p[1];
        Y[0]=v0.x; Y[1]=v0.y; Y[2]=v0.z; Y[3]=v0.w; Y[4]=v1.x; Y[5]=v1.y; Y[6]=v1.z; Y[7]=v1.w;
        p = (const float4*)(xb + 2 * NPTS + n0);
        v0 = p[0]; v1 = p[1];
        Z[0]=v0.x; Z[1]=v0.y; Z[2]=v0.z; Z[3]=v0.w; Z[4]=v1.x; Z[5]=v1.y; Z[6]=v1.z; Z[7]=v1.w;
        p = (const float4*)(ab + n0);
        v0 = p[0]; v1 = p[1];
        W[0]=v0.x; W[1]=v0.y; W[2]=v0.z; W[3]=v0.w; W[4]=v1.x; W[5]=v1.y; W[6]=v1.z; W[7]=v1.w;
    }
    int myrep = 0x7FFFFFFF;
    #pragma unroll
    for (int j = 0; j < 8; j++) {
        float a = W[j];
        float w = branch ? __fsub_rn(1.0f, a) : a;   // exact: a in {0,1}
        W[j] = w;
        X[j] = __fmul_rn(w, X[j]);
        Y[j] = __fmul_rn(w, Y[j]);
        Z[j] = __fmul_rn(w, Z[j]);
        if (w == 0.0f && (n0 + j) < myrep) myrep = n0 + j;
    }
    __syncthreads();
    if (myrep != 0x7FFFFFFF) atomicMin(&srep, myrep);
    __syncthreads();
    int rep = srep;

    unsigned cnt = 0, kmask = 0;
    #pragma unroll
    for (int j = 0; j < 8; j++) {
        bool kp = (W[j] != 0.0f) || ((n0 + j) == rep);
        if (kp) { kmask |= (1u << j); cnt++; }
    }
    unsigned inc = cnt;
    #pragma unroll
    for (int off = 1; off < 32; off <<= 1) {
        unsigned v = __shfl_up_sync(0xffffffffu, inc, off);
        if (lane >= off) inc += v;
    }
    if (lane == 31) sscan[wid] = inc;
    __syncthreads();
    if (wid == 0) {
        unsigned v = sscan[lane];
        #pragma unroll
        for (int off = 1; off < 32; off <<= 1) {
            unsigned u = __shfl_up_sync(0xffffffffu, v, off);
            if (lane >= off) v += u;
        }
        sscan[lane] = v;
    }
    __syncthreads();
    int m = (int)sscan[31];
    int o = (int)((wid ? sscan[wid - 1] : 0u) + (inc - cnt));
    #pragma unroll
    for (int j = 0; j < 8; j++) {
        if ((kmask >> j) & 1u) {
            sx[o] = X[j]; sy[o] = Y[j]; sz[o] = Z[j]; sid[o] = n0 + j;
            o++;
        }
    }
    for (int s2 = t; s2 < 4097; s2 += 1024) smd[s2] = 1e10f;
    __syncthreads();

    float px[4], py[4], pz[4], md[4];
    #pragma unroll
    for (int j = 0; j < 4; j++) {
        int sl = t + j * 1024;
        bool v = sl < m;
        px[j] = v ? sx[sl] : 0.0f;
        py[j] = v ? sy[sl] : 0.0f;
        pz[j] = v ? sz[sl] : 0.0f;
        md[j] = v ? 1e10f : 0.0f;
    }

    float* out_xyz  = out;                                           // [B,3,512]
    float* out_attn = out + BATCH * 3 * S_ALL + BATCH * 128 * S_ALL; // [B,1,512]

    int cur = 0;
    for (int k = 0; k < K; k++) {
        float bx = sx[cur], by = sy[cur], bz = sz[cur];
        if (t == 0) {
            int s = s_off + k;
            out_xyz[(b * 3 + 0) * S_ALL + s] = bx;
            out_xyz[(b * 3 + 1) * S_ALL + s] = by;
            out_xyz[(b * 3 + 2) * S_ALL + s] = bz;
            g_new_xyz[(b * S_ALL + s) * 3 + 0] = bx;
            g_new_xyz[(b * S_ALL + s) * 3 + 1] = by;
            g_new_xyz[(b * S_ALL + s) * 3 + 2] = bz;
            int orig = sid[cur];
            float att = branch ? ((orig == rep) ? 1.0f : 0.0f)
                               : ((orig == rep) ? 0.0f : 1.0f);
            out_attn[b * S_ALL + s] = att;
        }
        if (k == K - 1) break;

        unsigned long long bk = 0ull;
        #pragma unroll
        for (int j = 0; j < 4; j++) {
            float dx = __fsub_rn(px[j], bx);
            float dy = __fsub_rn(py[j], by);
            float dz = __fsub_rn(pz[j], bz);
            float d2 = __fadd_rn(__fadd_rn(__fmul_rn(dx, dx), __fmul_rn(dy, dy)),
                                 __fmul_rn(dz, dz));
            float mn = fminf(md[j], d2);
            md[j] = mn;
            int sl = t + j * 1024;
            unsigned long long key =
                ((unsigned long long)__float_as_uint(mn) << 32) |
                (unsigned long long)(0xFFFFFFFFu - (unsigned)sl);
            if (key > bk) bk = key;
        }
        for (int sl = 4096 + t; sl < m; sl += 1024) {
            float dx = __fsub_rn(sx[sl], bx);
            float dy = __fsub_rn(sy[sl], by);
            float dz = __fsub_rn(sz[sl], bz);
            float d2 = __fadd_rn(__fadd_rn(__fmul_rn(dx, dx), __fmul_rn(dy, dy)),
                                 __fmul_rn(dz, dz));
            float mn = fminf(smd[sl - 4096], d2);
            smd[sl - 4096] = mn;
            unsigned long long key =
                ((unsigned long long)__float_as_uint(mn) << 32) |
                (unsigned long long)(0xFFFFFFFFu - (unsigned)sl);
            if (key > bk) bk = key;
        }
        unsigned vb   = (unsigned)(bk >> 32);
        unsigned vmax = __reduce_max_sync(0xffffffffu, vb);
        unsigned lo   = (vb == vmax) ? (unsigned)bk : 0u;
        unsigned lmax = __reduce_max_sync(0xffffffffu, lo);
        if (lane == 0) sred[k & 1][wid] = ((unsigned long long)vmax << 32) | lmax;
        __syncthreads();
        unsigned long long e = sred[k & 1][lane];
        vb   = (unsigned)(e >> 32);
        vmax = __reduce_max_sync(0xffffffffu, vb);
        lo   = (vb == vmax) ? (unsigned)e : 0u;
        lmax = __reduce_max_sync(0xffffffffu, lo);
        cur  = (int)(0xFFFFFFFFu - lmax);
    }
}

// ================= ball query + grouping + MLP + maxpool: 128-thread CTA per (b,s) =================
// Mr=8 outputs x Nr=4 samples per thread: feature-LDS redundancy halves vs Mr=4.
__global__ __launch_bounds__(128, 6) void group_mlp_kernel(
    const float* __restrict__ xyz,
    const float* __restrict__ b0,
    const float* __restrict__ w1, const float* __restrict__ b1,
    const float* __restrict__ w2, const float* __restrict__ b2,
    float* __restrict__ out)
{
    __shared__ __align__(16) float sfeat[68 * 64];   // [c][k], reused as h2
    __shared__ __align__(16) float sh1[64 * 64];     // [c][k]
    __shared__ int sidx[64];
    __shared__ int swarp[4];

    int t = threadIdx.x;
    int wid = t >> 5, lane = t & 31;
    unsigned lmaskb = (1u << lane) - 1u;

    int bs = blockIdx.x;
    int b = bs >> 9;
    int s = bs & 511;

    const float* xb = xyz + (size_t)b * 3 * NPTS;
    float qx = g_new_xyz[(b * S_ALL + s) * 3 + 0];
    float qy = g_new_xyz[(b * S_ALL + s) * 3 + 1];
    float qz = g_new_xyz[(b * S_ALL + s) * 3 + 2];
    const float R2 = (float)(0.4 * 0.4);

    if (t < 64) { sidx[t] = -1; sfeat[67 * 64 + t] = 0.0f; }
    __syncthreads();

    // ---- ball query: ordered first-64 collection, 64 coalesced rounds (early break) ----
    int total = 0;
    for (int mm = 0; mm < 64; mm++) {
        int n = mm * 128 + t;
        float dx = __fsub_rn(qx, xb[n]);
        float dy = __fsub_rn(qy, xb[NPTS + n]);
        float dz = __fsub_rn(qz, xb[2 * NPTS + n]);
        float d2 = __fadd_rn(__fadd_rn(__fmul_rn(dx, dx), __fmul_rn(dy, dy)),
                             __fmul_rn(dz, dz));
        bool pred = d2 < R2;
        unsigned ball = __ballot_sync(0xffffffffu, pred);
        if (lane == 0) swarp[wid] = __popc(ball);
        __syncthreads();
        int off = total, all = 0;
        #pragma unroll
        for (int w = 0; w < 4; w++) {
            int v = swarp[w];
            all += v;
            if (w < wid) off += v;
        }
        if (pred) {
            int slot = off + __popc(ball & lmaskb);
            if (slot < 64) sidx[slot] = n;
        }
        total += all;
        __syncthreads();
        if (total >= 64) break;
    }

    // ---- feat [68][64]: c0..2 = grouped_xyz - q (pad 0), c3..66 = points (pad idx N-1) ----
    if (t < 64) {
        int idx = sidx[t];
        float gx = (idx >= 0) ? xb[idx] : 0.0f;
        float gy = (idx >= 0) ? xb[NPTS + idx] : 0.0f;
        float gz = (idx >= 0) ? xb[2 * NPTS + idx] : 0.0f;
        sfeat[0 * 64 + t] = __fsub_rn(gx, qx);
        sfeat[1 * 64 + t] = __fsub_rn(gy, qy);
        sfeat[2 * 64 + t] = __fsub_rn(gz, qz);
    }
    {
        int kk = t & 63, fq = t >> 6;            // 2 threads per sample row, 8 float4 each
        int idx = sidx[kk];
        int gi = (idx >= 0) ? idx : (NPTS - 1);
        const float4* row = (const float4*)(g_pts_t + ((size_t)b * NPTS + gi) * DF);
        #pragma unroll
        for (int f2 = 0; f2 < 8; f2++) {
            int f = fq * 8 + f2;
            float4 v = row[f];
            sfeat[(3 + 4 * f + 0) * 64 + kk] = v.x;
            sfeat[(3 + 4 * f + 1) * 64 + kk] = v.y;
            sfeat[(3 + 4 * f + 2) * 64 + kk] = v.z;
            sfeat[(3 + 4 * f + 3) * 64 + kk] = v.w;
        }
    }
    __syncthreads();

    int og = t >> 4;              // 0..7  (8 outputs each)
    int kb = (t & 15) * 4;        // 0..60 (4 samples each)

    // ---- layer1: 68(pad) -> 64, relu ----
    {
        const float4* w0p = (const float4*)g_w0p + og * 8 * 17;  // 8 rows of 17 float4
        const float*  fp  = sfeat + kb;
        float acc[8][4];
        #pragma unroll
        for (int i = 0; i < 8; i++) {
            float bv = __ldg(&b0[og * 8 + i]);
            acc[i][0] = acc[i][1] = acc[i][2] = acc[i][3] = bv;
        }
        #pragma unroll
        for (int c4 = 0; c4 < 17; c4++) {
            float4 f0 = *(const float4*)(fp + (c4 * 4 + 0) * 64);
            float4 f1 = *(const float4*)(fp + (c4 * 4 + 1) * 64);
            float4 f2 = *(const float4*)(fp + (c4 * 4 + 2) * 64);
            float4 f3 = *(const float4*)(fp + (c4 * 4 + 3) * 64);
            #pragma unroll
            for (int i = 0; i < 8; i++) {
                float4 w = __ldg(&w0p[i * 17 + c4]);
                acc[i][0] = fmaf(w.x, f0.x, acc[i][0]); acc[i][0] = fmaf(w.y, f1.x, acc[i][0]);
                acc[i][0] = fmaf(w.z, f2.x, acc[i][0]); acc[i][0] = fmaf(w.w, f3.x, acc[i][0]);
                acc[i][1] = fmaf(w.x, f0.y, acc[i][1]); acc[i][1] = fmaf(w.y, f1.y, acc[i][1]);
                acc[i][1] = fmaf(w.z, f2.y, acc[i][1]); acc[i][1] = fmaf(w.w, f3.y, acc[i][1]);
                acc[i][2] = fmaf(w.x, f0.z, acc[i][2]); acc[i][2] = fmaf(w.y, f1.z, acc[i][2]);
                acc[i][2] = fmaf(w.z, f2.z, acc[i][2]); acc[i][2] = fmaf(w.w, f3.z, acc[i][2]);
                acc[i][3] = fmaf(w.x, f0.w, acc[i][3]); acc[i][3] = fmaf(w.y, f1.w, acc[i][3]);
                acc[i][3] = fmaf(w.z, f2.w, acc[i][3]); acc[i][3] = fmaf(w.w, f3.w, acc[i][3]);
            }
        }
        #pragma unroll
        for (int i = 0; i < 8; i++) {
            float4 r;
            r.x = fmaxf(acc[i][0], 0.f); r.y = fmaxf(acc[i][1], 0.f);
            r.z = fmaxf(acc[i][2], 0.f); r.w = fmaxf(acc[i][3], 0.f);
            *(float4*)(sh1 + (og * 8 + i) * 64 + kb) = r;
        }
    }
    __syncthreads();

    // ---- layer2: 64 -> 64, relu ----
    {
        const float4* w1p = (const float4*)w1 + og * 8 * 16;     // 8 rows of 16 float4
        const float*  fp  = sh1 + kb;
        float acc[8][4];
        #pragma unroll
        for (int i = 0; i < 8; i++) {
            float bv = __ldg(&b1[og * 8 + i]);
            acc[i][0] = acc[i][1] = acc[i][2] = acc[i][3] = bv;
        }
        #pragma unroll
        for (int c4 = 0; c4 < 16; c4++) {
            float4 f0 = *(const float4*)(fp + (c4 * 4 + 0) * 64);
            float4 f1 = *(const float4*)(fp + (c4 * 4 + 1) * 64);
            float4 f2 = *(const float4*)(fp + (c4 * 4 + 2) * 64);
            float4 f3 = *(const float4*)(fp + (c4 * 4 + 3) * 64);
            #pragma unroll
            for (int i = 0; i < 8; i++) {
                float4 w = __ldg(&w1p[i * 16 + c4]);
                acc[i][0] = fmaf(w.x, f0.x, acc[i][0]); acc[i][0] = fmaf(w.y, f1.x, acc[i][0]);
                acc[i][0] = fmaf(w.z, f2.x, acc[i][0]); acc[i][0] = fmaf(w.w, f3.x, acc[i][0]);
                acc[i][1] = fmaf(w.x, f0.y, acc[i][1]); acc[i][1] = fmaf(w.y, f1.y, acc[i][1]);
                acc[i][1] = fmaf(w.z, f2.y, acc[i][1]); acc[i][1] = fmaf(w.w, f3.y, acc[i][1]);
                acc[i][2] = fmaf(w.x, f0.z, acc[i][2]); acc[i][2] = fmaf(w.y, f1.z, acc[i][2]);
                acc[i][2] = fmaf(w.z, f2.z, acc[i][2]); acc[i][2] = fmaf(w.w, f3.z, acc[i][2]);
                acc[i][3] = fmaf(w.x, f0.w, acc[i][3]); acc[i][3] = fmaf(w.y, f1.w, acc[i][3]);
                acc[i][3] = fmaf(w.z, f2.w, acc[i][3]); acc[i][3] = fmaf(w.w, f3.w, acc[i][3]);
            }
        }
        __syncthreads();   // all layer-1 sfeat reads done before overwrite
        #pragma unroll
        for (int i = 0; i < 8; i++) {
            float4 r;
            r.x = fmaxf(acc[i][0], 0.f); r.y = fmaxf(acc[i][1], 0.f);
            r.z = fmaxf(acc[i][2], 0.f); r.w = fmaxf(acc[i][3], 0.f);
            *(float4*)(sfeat + (og * 8 + i) * 64 + kb) = r;
        }
    }
    __syncthreads();

    // ---- layer3: 64 -> 128, relu + maxpool; two passes of 64 outputs ----
    {
        float* out_points = out + BATCH * 3 * S_ALL;   // [B,128,512]
        const float* fp = sfeat + kb;
        #pragma unroll 1
        for (int h = 0; h < 2; h++) {
            const float4* w2p = (const float4*)w2 + (h * 64 + og * 8) * 16;
            float acc[8][4];
            #pragma unroll
            for (int i = 0; i < 8; i++) {
                float bv = __ldg(&b2[h * 64 + og * 8 + i]);
                acc[i][0] = acc[i][1] = acc[i][2] = acc[i][3] = bv;
            }
            #pragma unroll
            for (int c4 = 0; c4 < 16; c4++) {
                float4 f0 = *(const float4*)(fp + (c4 * 4 + 0) * 64);
                float4 f1 = *(const float4*)(fp + (c4 * 4 + 1) * 64);
                float4 f2 = *(const float4*)(fp + (c4 * 4 + 2) * 64);
                float4 f3 = *(const float4*)(fp + (c4 * 4 + 3) * 64);
                #pragma unroll
                for (int i = 0; i < 8; i++) {
                    float4 w = __ldg(&w2p[i * 16 + c4]);
                    acc[i][0] = fmaf(w.x, f0.x, acc[i][0]); acc[i][0] = fmaf(w.y, f1.x, acc[i][0]);
                    acc[i][0] = fmaf(w.z, f2.x, acc[i][0]); acc[i][0] = fmaf(w.w, f3.x, acc[i][0]);
                    acc[i][1] = fmaf(w.x, f0.y, acc[i][1]); acc[i][1] = fmaf(w.y, f1.y, acc[i][1]);
                    acc[i][1] = fmaf(w.z, f2.y, acc[i][1]); acc[i][1] = fmaf(w.w, f3.y, acc[i][1]);
                    acc[i][2] = fmaf(w.x, f0.z, acc[i][2]); acc[i][2] = fmaf(w.y, f1.z, acc[i][2]);
                    acc[i][2] = fmaf(w.z, f2.z, acc[i][2]); acc[i][2] = fmaf(w.w, f3.z, acc[i][2]);
                    acc[i][3] = fmaf(w.x, f0.w, acc[i][3]); acc[i][3] = fmaf(w.y, f1.w, acc[i][3]);
                    acc[i][3] = fmaf(w.z, f2.w, acc[i][3]); acc[i][3] = fmaf(w.w, f3.w, acc[i][3]);
                }
            }
            #pragma unroll
            for (int i = 0; i < 8; i++) {
                float mv = fmaxf(fmaxf(acc[i][0], acc[i][1]), fmaxf(acc[i][2], acc[i][3]));
                #pragma unroll
                for (int off = 1; off < 16; off <<= 1)
                    mv = fmaxf(mv, __shfl_xor_sync(0xffffffffu, mv, off));
                if ((t & 15) == 0)
                    out_points[((size_t)b * 128 + h * 64 + og * 8 + i) * S_ALL + s] = fmaxf(mv, 0.0f);
            }
        }
    }
}

extern "C" void kernel_launch(void* const* d_in, const int* in_sizes, int n_in,
                              void* d_out, int out_size) {
    const float* xyz       = (const float*)d_in[0];
    const float* points    = (const float*)d_in[1];
    const float* attention = (const float*)d_in[2];
    const float* w0 = (const float*)d_in[3];
    const float* b0 = (const float*)d_in[4];
    const float* w1 = (const float*)d_in[5];
    const float* b1 = (const float*)d_in[6];
    const float* w2 = (const float*)d_in[7];
    const float* b2 = (const float*)d_in[8];
    float* out = (float*)d_out;

    const int fps_smem = 8193 * 16 + 4097 * 4;   // (sx,sy,sz,sid)[8193] + smd[4097]
    cudaFuncSetAttribute(fps_kernel, cudaFuncAttributeMaxDynamicSharedMemorySize, fps_smem);

    prep_w0_kernel<<<17, 256>>>(w0);
    transpose_kernel<<<dim3(256, 2, 8), dim3(32, 32)>>>(points);
    fps_kernel<<<16, 1024, fps_smem>>>(xyz, attention, out);
    group_mlp_kernel<<<BATCH * S_ALL, 128>>>(xyz, b0, w1, b1, w2, b2, out);
}

// round 7
// speedup vs baseline: 1.1184x; 1.1184x over previous
#include <cuda_runtime.h>

#define NPTS   8192
#define BATCH  8
#define S_ALL  512
#define K_ATTN 128
#define K_NONE 384
#define DF     64

// ---------------- scratch (static device arrays; no allocation) ----------------
__device__ float g_pts_t[BATCH * NPTS * DF];      // points transposed to [B][N][64]
__device__ float g_new_xyz[BATCH * S_ALL * 3];    // sampled (masked) coords [B][S][3]
__device__ float g_w0p[64 * 68];                  // w0 padded to [64][68]

// ---------------- tiny prep: pad w0 rows 67 -> 68 ----------------
__global__ void prep_w0_kernel(const float* __restrict__ w0) {
    int i = blockIdx.x * 256 + threadIdx.x;
    if (i < 64 * 68) {
        int r = i / 68, c = i % 68;
        g_w0p[i] = (c < 67) ? w0[r * 67 + c] : 0.0f;
    }
}

// ---------------- transpose points [B,64,N] -> [B,N,64] ----------------
__global__ void transpose_kernel(const float* __restrict__ points) {
    __shared__ float tile[32][33];
    int b  = blockIdx.z;
    int c0 = blockIdx.y * 32;
    int n0 = blockIdx.x * 32;
    int tx = threadIdx.x, ty = threadIdx.y;
    tile[ty][tx] = points[(b * DF + c0 + ty) * NPTS + n0 + tx];
    __syncthreads();
    g_pts_t[(b * NPTS + n0 + ty) * DF + c0 + tx] = tile[tx][ty];
}

// ---------------- FPS with origin-duplicate compression (one branch per launch) ----------------
// branch 0: attn*xyz, K=128 -> s in [0,128); branch 1: (1-attn)*xyz, K=384 -> s in [128,512)
template <int BRANCH>
__global__ __launch_bounds__(1024) void fps_kernel(
    const float* __restrict__ xyz, const float* __restrict__ attention,
    float* __restrict__ out)
{
    extern __shared__ float dsm[];
    float* sx  = dsm;                    // [8193]
    float* sy  = sx + 8193;
    float* sz  = sy + 8193;
    int*   sid = (int*)(sz + 8193);      // [8193]
    float* smd = (float*)(sid + 8193);   // [4097] overflow min-dist

    __shared__ unsigned sscan[32];
    __shared__ unsigned long long sred[2][32];
    __shared__ int srep;

    int b = blockIdx.x;
    const int K     = BRANCH ? K_NONE : K_ATTN;
    const int s_off = BRANCH ? K_ATTN : 0;
    int t = threadIdx.x;
    int wid = t >> 5, lane = t & 31;

    const float* xb = xyz + (size_t)b * 3 * NPTS;
    const float* ab = attention + (size_t)b * NPTS;

    if (t == 0) srep = 0x7FFFFFFF;

    int n0 = t * 8;
    float X[8], Y[8], Z[8], W[8];
    {
        const float4* p = (const float4*)(xb + n0);
        float4 v0 = p[0], v1 = p[1];
        X[0]=v0.x; X[1]=v0.y; X[2]=v0.z; X[3]=v0.w; X[4]=v1.x; X[5]=v1.y; X[6]=v1.z; X[7]=v1.w;
        p = (const float4*)(xb + NPTS + n0);
        v0 = p[0]; v1 = p[1];
        Y[0]=v0.x; Y[1]=v0.y; Y[2]=v0.z; Y[3]=v0.w; Y[4]=v1.x; Y[5]=v1.y; Y[6]=v1.z; Y[7]=v1.w;
        p = (const float4*)(xb + 2 * NPTS + n0);
        v0 = p[0]; v1 = p[1];
        Z[0]=v0.x; Z[1]=v0.y; Z[2]=v0.z; Z[3]=v0.w; Z[4]=v1.x; Z[5]=v1.y; Z[6]=v1.z; Z[7]=v1.w;
        p = (const float4*)(ab + n0);
        v0 = p[0]; v1 = p[1];
        W[0]=v0.x; W[1]=v0.y; W[2]=v0.z; W[3]=v0.w; W[4]=v1.x; W[5]=v1.y; W[6]=v1.z; W[7]=v1.w;
    }
    int myrep = 0x7FFFFFFF;
    #pragma unroll
    for (int j = 0; j < 8; j++) {
        float a = W[j];
        float w = BRANCH ? __fsub_rn(1.0f, a) : a;   // exact: a in {0,1}
        W[j] = w;
        X[j] = __fmul_rn(w, X[j]);
        Y[j] = __fmul_rn(w, Y[j]);
        Z[j] = __fmul_rn(w, Z[j]);
        if (w == 0.0f && (n0 + j) < myrep) myrep = n0 + j;
    }
    __syncthreads();
    if (myrep != 0x7FFFFFFF) atomicMin(&srep, myrep);
    __syncthreads();
    int rep = srep;

    unsigned cnt = 0, kmask = 0;
    #pragma unroll
    for (int j = 0; j < 8; j++) {
        bool kp = (W[j] != 0.0f) || ((n0 + j) == rep);
        if (kp) { kmask |= (1u << j); cnt++; }
    }
    unsigned inc = cnt;
    #pragma unroll
    for (int off = 1; off < 32; off <<= 1) {
        unsigned v = __shfl_up_sync(0xffffffffu, inc, off);
        if (lane >= off) inc += v;
    }
    if (lane == 31) sscan[wid] = inc;
    __syncthreads();
    if (wid == 0) {
        unsigned v = sscan[lane];
        #pragma unroll
        for (int off = 1; off < 32; off <<= 1) {
            unsigned u = __shfl_up_sync(0xffffffffu, v, off);
            if (lane >= off) v += u;
        }
        sscan[lane] = v;
    }
    __syncthreads();
    int m = (int)sscan[31];
    int o = (int)((wid ? sscan[wid - 1] : 0u) + (inc - cnt));
    #pragma unroll
    for (int j = 0; j < 8; j++) {
        if ((kmask >> j) & 1u) {
            sx[o] = X[j]; sy[o] = Y[j]; sz[o] = Z[j]; sid[o] = n0 + j;
            o++;
        }
    }
    for (int s2 = t; s2 < 4097; s2 += 1024) smd[s2] = 1e10f;
    __syncthreads();

    float px[4], py[4], pz[4], md[4];
    #pragma unroll
    for (int j = 0; j < 4; j++) {
        int sl = t + j * 1024;
        bool v = sl < m;
        px[j] = v ? sx[sl] : 0.0f;
        py[j] = v ? sy[sl] : 0.0f;
        pz[j] = v ? sz[sl] : 0.0f;
        md[j] = v ? 1e10f : 0.0f;
    }

    float* out_xyz  = out;                                           // [B,3,512]
    float* out_attn = out + BATCH * 3 * S_ALL + BATCH * 128 * S_ALL; // [B,1,512]

    int cur = 0;
    for (int k = 0; k < K; k++) {
        float bx = sx[cur], by = sy[cur], bz = sz[cur];
        if (t == 0) {
            int s = s_off + k;
            out_xyz[(b * 3 + 0) * S_ALL + s] = bx;
            out_xyz[(b * 3 + 1) * S_ALL + s] = by;
            out_xyz[(b * 3 + 2) * S_ALL + s] = bz;
            g_new_xyz[(b * S_ALL + s) * 3 + 0] = bx;
            g_new_xyz[(b * S_ALL + s) * 3 + 1] = by;
            g_new_xyz[(b * S_ALL + s) * 3 + 2] = bz;
            int orig = sid[cur];
            float att = BRANCH ? ((orig == rep) ? 1.0f : 0.0f)
                               : ((orig == rep) ? 0.0f : 1.0f);
            out_attn[b * S_ALL + s] = att;
        }
        if (k == K - 1) break;

        unsigned long long bk = 0ull;
        #pragma unroll
        for (int j = 0; j < 4; j++) {
            float dx = __fsub_rn(px[j], bx);
            float dy = __fsub_rn(py[j], by);
            float dz = __fsub_rn(pz[j], bz);
            float d2 = __fadd_rn(__fadd_rn(__fmul_rn(dx, dx), __fmul_rn(dy, dy)),
                                 __fmul_rn(dz, dz));
            float mn = fminf(md[j], d2);
            md[j] = mn;
            int sl = t + j * 1024;
            unsigned long long key =
                ((unsigned long long)__float_as_uint(mn) << 32) |
                (unsigned long long)(0xFFFFFFFFu - (unsigned)sl);
            if (key > bk) bk = key;
        }
        for (int sl = 4096 + t; sl < m; sl += 1024) {
            float dx = __fsub_rn(sx[sl], bx);
            float dy = __fsub_rn(sy[sl], by);
            float dz = __fsub_rn(sz[sl], bz);
            float d2 = __fadd_rn(__fadd_rn(__fmul_rn(dx, dx), __fmul_rn(dy, dy)),
                                 __fmul_rn(dz, dz));
            float mn = fminf(smd[sl - 4096], d2);
            smd[sl - 4096] = mn;
            unsigned long long key =
                ((unsigned long long)__float_as_uint(mn) << 32) |
                (unsigned long long)(0xFFFFFFFFu - (unsigned)sl);
            if (key > bk) bk = key;
        }
        unsigned vb   = (unsigned)(bk >> 32);
        unsigned vmax = __reduce_max_sync(0xffffffffu, vb);
        unsigned lo   = (vb == vmax) ? (unsigned)bk : 0u;
        unsigned lmax = __reduce_max_sync(0xffffffffu, lo);
        if (lane == 0) sred[k & 1][wid] = ((unsigned long long)vmax << 32) | lmax;
        __syncthreads();
        unsigned long long e = sred[k & 1][lane];
        vb   = (unsigned)(e >> 32);
        vmax = __reduce_max_sync(0xffffffffu, vb);
        lo   = (vb == vmax) ? (unsigned)e : 0u;
        lmax = __reduce_max_sync(0xffffffffu, lo);
        cur  = (int)(0xFFFFFFFFu - lmax);
    }
}

// ================= ball query + grouping + MLP + maxpool: one CTA per (b,s) =================
// R5 config (Mr=4, 256 threads) — best measured. S_BASE/NS select the site range.
template <int S_BASE, int NS>
__global__ __launch_bounds__(256, 4) void group_mlp_kernel(
    const float* __restrict__ xyz,
    const float* __restrict__ b0,
    const float* __restrict__ w1, const float* __restrict__ b1,
    const float* __restrict__ w2, const float* __restrict__ b2,
    float* __restrict__ out)
{
    __shared__ __align__(16) float sfeat[68 * 64];   // [c][k], reused as h2
    __shared__ __align__(16) float sh1[64 * 64];     // [c][k]
    __shared__ int sidx[64];
    __shared__ int swarp[8];

    int t = threadIdx.x;
    int wid = t >> 5, lane = t & 31;
    unsigned lmaskb = (1u << lane) - 1u;

    int bs = blockIdx.x;
    int b = bs / NS;
    int s = S_BASE + (bs - b * NS);

    const float* xb = xyz + (size_t)b * 3 * NPTS;
    float qx = g_new_xyz[(b * S_ALL + s) * 3 + 0];
    float qy = g_new_xyz[(b * S_ALL + s) * 3 + 1];
    float qz = g_new_xyz[(b * S_ALL + s) * 3 + 2];
    const float R2 = (float)(0.4 * 0.4);

    if (t < 64) { sidx[t] = -1; sfeat[67 * 64 + t] = 0.0f; }
    __syncthreads();

    // ---- ball query ----
    int total = 0;
    for (int mm = 0; mm < 32; mm++) {
        int n = mm * 256 + t;
        float dx = __fsub_rn(qx, xb[n]);
        float dy = __fsub_rn(qy, xb[NPTS + n]);
        float dz = __fsub_rn(qz, xb[2 * NPTS + n]);
        float d2 = __fadd_rn(__fadd_rn(__fmul_rn(dx, dx), __fmul_rn(dy, dy)),
                             __fmul_rn(dz, dz));
        bool pred = d2 < R2;
        unsigned ball = __ballot_sync(0xffffffffu, pred);
        if (lane == 0) swarp[wid] = __popc(ball);
        __syncthreads();
        int off = total, all = 0;
        #pragma unroll
        for (int w = 0; w < 8; w++) {
            int v = swarp[w];
            all += v;
            if (w < wid) off += v;
        }
        if (pred) {
            int slot = off + __popc(ball & lmaskb);
            if (slot < 64) sidx[slot] = n;
        }
        total += all;
        __syncthreads();
        if (total >= 64) break;
    }

    // ---- feat [68][64] ----
    if (t < 192) {
        int c = t >> 6, kk = t & 63;
        int idx = sidx[kk];
        float q = (c == 0) ? qx : ((c == 1) ? qy : qz);
        float g = (idx >= 0) ? xb[c * NPTS + idx] : 0.0f;
        sfeat[c * 64 + kk] = __fsub_rn(g, q);
    }
    {
        int kk = t & 63, fq = t >> 6;
        int idx = sidx[kk];
        int gi = (idx >= 0) ? idx : (NPTS - 1);
        const float4* row = (const float4*)(g_pts_t + ((size_t)b * NPTS + gi) * DF);
        #pragma unroll
        for (int f2 = 0; f2 < 4; f2++) {
            int f = fq * 4 + f2;
            float4 v = row[f];
            sfeat[(3 + 4 * f + 0) * 64 + kk] = v.x;
            sfeat[(3 + 4 * f + 1) * 64 + kk] = v.y;
            sfeat[(3 + 4 * f + 2) * 64 + kk] = v.z;
            sfeat[(3 + 4 * f + 3) * 64 + kk] = v.w;
        }
    }
    __syncthreads();

    int og = t >> 4;              // 0..15
    int kb = (t & 15) * 4;        // 0..60

    // ---- layer1: 68(pad) -> 64, relu ----
    {
        const float4* w0p = (const float4*)g_w0p + og * 68;  // 4 rows of 17 float4
        const float*  fp  = sfeat + kb;
        float acc[4][4];
        #pragma unroll
        for (int i = 0; i < 4; i++) {
            float bv = __ldg(&b0[og * 4 + i]);
            acc[i][0] = acc[i][1] = acc[i][2] = acc[i][3] = bv;
        }
        #pragma unroll
        for (int c4 = 0; c4 < 17; c4++) {
            float4 f0 = *(const float4*)(fp + (c4 * 4 + 0) * 64);
            float4 f1 = *(const float4*)(fp + (c4 * 4 + 1) * 64);
            float4 f2 = *(const float4*)(fp + (c4 * 4 + 2) * 64);
            float4 f3 = *(const float4*)(fp + (c4 * 4 + 3) * 64);
            #pragma unroll
            for (int i = 0; i < 4; i++) {
                float4 w = __ldg(&w0p[i * 17 + c4]);
                acc[i][0] = fmaf(w.x, f0.x, acc[i][0]); acc[i][0] = fmaf(w.y, f1.x, acc[i][0]);
                acc[i][0] = fmaf(w.z, f2.x, acc[i][0]); acc[i][0] = fmaf(w.w, f3.x, acc[i][0]);
                acc[i][1] = fmaf(w.x, f0.y, acc[i][1]); acc[i][1] = fmaf(w.y, f1.y, acc[i][1]);
                acc[i][1] = fmaf(w.z, f2.y, acc[i][1]); acc[i][1] = fmaf(w.w, f3.y, acc[i][1]);
                acc[i][2] = fmaf(w.x, f0.z, acc[i][2]); acc[i][2] = fmaf(w.y, f1.z, acc[i][2]);
                acc[i][2] = fmaf(w.z, f2.z, acc[i][2]); acc[i][2] = fmaf(w.w, f3.z, acc[i][2]);
                acc[i][3] = fmaf(w.x, f0.w, acc[i][3]); acc[i][3] = fmaf(w.y, f1.w, acc[i][3]);
                acc[i][3] = fmaf(w.z, f2.w, acc[i][3]); acc[i][3] = fmaf(w.w, f3.w, acc[i][3]);
            }
        }
        #pragma unroll
        for (int i = 0; i < 4; i++) {
            float4 r;
            r.x = fmaxf(acc[i][0], 0.f); r.y = fmaxf(acc[i][1], 0.f);
            r.z = fmaxf(acc[i][2], 0.f); r.w = fmaxf(acc[i][3], 0.f);
            *(float4*)(sh1 + (og * 4 + i) * 64 + kb) = r;
        }
    }
    __syncthreads();

    // ---- layer2: 64 -> 64, relu ----
    {
        const float4* w1p = (const float4*)w1 + og * 64;     // 4 rows of 16 float4
        const float*  fp  = sh1 + kb;
        float acc[4][4];
        #pragma unroll
        for (int i = 0; i < 4; i++) {
            float bv = __ldg(&b1[og * 4 + i]);
            acc[i][0] = acc[i][1] = acc[i][2] = acc[i][3] = bv;
        }
        #pragma unroll
        for (int c4 = 0; c4 < 16; c4++) {
            float4 f0 = *(const float4*)(fp + (c4 * 4 + 0) * 64);
            float4 f1 = *(const float4*)(fp + (c4 * 4 + 1) * 64);
            float4 f2 = *(const float4*)(fp + (c4 * 4 + 2) * 64);
            float4 f3 = *(const float4*)(fp + (c4 * 4 + 3) * 64);
            #pragma unroll
            for (int i = 0; i < 4; i++) {
                float4 w = __ldg(&w1p[i * 16 + c4]);
                acc[i][0] = fmaf(w.x, f0.x, acc[i][0]); acc[i][0] = fmaf(w.y, f1.x, acc[i][0]);
                acc[i][0] = fmaf(w.z, f2.x, acc[i][0]); acc[i][0] = fmaf(w.w, f3.x, acc[i][0]);
                acc[i][1] = fmaf(w.x, f0.y, acc[i][1]); acc[i][1] = fmaf(w.y, f1.y, acc[i][1]);
                acc[i][1] = fmaf(w.z, f2.y, acc[i][1]); acc[i][1] = fmaf(w.w, f3.y, acc[i][1]);
                acc[i][2] = fmaf(w.x, f0.z, acc[i][2]); acc[i][2] = fmaf(w.y, f1.z, acc[i][2]);
                acc[i][2] = fmaf(w.z, f2.z, acc[i][2]); acc[i][2] = fmaf(w.w, f3.z, acc[i][2]);
                acc[i][3] = fmaf(w.x, f0.w, acc[i][3]); acc[i][3] = fmaf(w.y, f1.w, acc[i][3]);
                acc[i][3] = fmaf(w.z, f2.w, acc[i][3]); acc[i][3] = fmaf(w.w, f3.w, acc[i][3]);
            }
        }
        __syncthreads();   // all layer-1 sfeat reads done before overwrite
        #pragma unroll
        for (int i = 0; i < 4; i++) {
            float4 r;
            r.x = fmaxf(acc[i][0], 0.f); r.y = fmaxf(acc[i][1], 0.f);
            r.z = fmaxf(acc[i][2], 0.f); r.w = fmaxf(acc[i][3], 0.f);
            *(float4*)(sfeat + (og * 4 + i) * 64 + kb) = r;
        }
    }
    __syncthreads();

    // ---- layer3: 64 -> 128, relu + maxpool; two passes of 64 outputs ----
    {
        float* out_points = out + BATCH * 3 * S_ALL;   // [B,128,512]
        const float* fp = sfeat + kb;
        #pragma unroll 1
        for (int h = 0; h < 2; h++) {
            const float4* w2p = (const float4*)w2 + (h * 64 + og * 4) * 16;
            float acc[4][4];
            #pragma unroll
            for (int i = 0; i < 4; i++) {
                float bv = __ldg(&b2[h * 64 + og * 4 + i]);
                acc[i][0] = acc[i][1] = acc[i][2] = acc[i][3] = bv;
            }
            #pragma unroll
            for (int c4 = 0; c4 < 16; c4++) {
                float4 f0 = *(const float4*)(fp + (c4 * 4 + 0) * 64);
                float4 f1 = *(const float4*)(fp + (c4 * 4 + 1) * 64);
                float4 f2 = *(const float4*)(fp + (c4 * 4 + 2) * 64);
                float4 f3 = *(const float4*)(fp + (c4 * 4 + 3) * 64);
                #pragma unroll
                for (int i = 0; i < 4; i++) {
                    float4 w = __ldg(&w2p[i * 16 + c4]);
                    acc[i][0] = fmaf(w.x, f0.x, acc[i][0]); acc[i][0] = fmaf(w.y, f1.x, acc[i][0]);
                    acc[i][0] = fmaf(w.z, f2.x, acc[i][0]); acc[i][0] = fmaf(w.w, f3.x, acc[i][0]);
                    acc[i][1] = fmaf(w.x, f0.y, acc[i][1]); acc[i][1] = fmaf(w.y, f1.y, acc[i][1]);
                    acc[i][1] = fmaf(w.z, f2.y, acc[i][1]); acc[i][1] = fmaf(w.w, f3.y, acc[i][1]);
                    acc[i][2] = fmaf(w.x, f0.z, acc[i][2]); acc[i][2] = fmaf(w.y, f1.z, acc[i][2]);
                    acc[i][2] = fmaf(w.z, f2.z, acc[i][2]); acc[i][2] = fmaf(w.w, f3.z, acc[i][2]);
                    acc[i][3] = fmaf(w.x, f0.w, acc[i][3]); acc[i][3] = fmaf(w.y, f1.w, acc[i][3]);
                    acc[i][3] = fmaf(w.z, f2.w, acc[i][3]); acc[i][3] = fmaf(w.w, f3.w, acc[i][3]);
                }
            }
            #pragma unroll
            for (int i = 0; i < 4; i++) {
                float mv = fmaxf(fmaxf(acc[i][0], acc[i][1]), fmaxf(acc[i][2], acc[i][3]));
                #pragma unroll
                for (int off = 1; off < 16; off <<= 1)
                    mv = fmaxf(mv, __shfl_xor_sync(0xffffffffu, mv, off));
                if ((t & 15) == 0)
                    out_points[((size_t)b * 128 + h * 64 + og * 4 + i) * S_ALL + s] = fmaxf(mv, 0.0f);
            }
        }
    }
}

extern "C" void kernel_launch(void* const* d_in, const int* in_sizes, int n_in,
                              void* d_out, int out_size) {
    const float* xyz       = (const float*)d_in[0];
    const float* points    = (const float*)d_in[1];
    const float* attention = (const float*)d_in[2];
    const float* w0 = (const float*)d_in[3];
    const float* b0 = (const float*)d_in[4];
    const float* w1 = (const float*)d_in[5];
    const float* b1 = (const float*)d_in[6];
    const float* w2 = (const float*)d_in[7];
    const float* b2 = (const float*)d_in[8];
    float* out = (float*)d_out;

    // one-time stream/event infra (resource setup only; identical launches every call)
    static cudaStream_t sA = nullptr, sB = nullptr;
    static cudaEvent_t eFork = nullptr, eT = nullptr, eA = nullptr, eB = nullptr;
    if (sA == nullptr) {
        cudaStreamCreateWithFlags(&sA, cudaStreamNonBlocking);
        cudaStreamCreateWithFlags(&sB, cudaStreamNonBlocking);
        cudaEventCreateWithFlags(&eFork, cudaEventDisableTiming);
        cudaEventCreateWithFlags(&eT,    cudaEventDisableTiming);
        cudaEventCreateWithFlags(&eA,    cudaEventDisableTiming);
        cudaEventCreateWithFlags(&eB,    cudaEventDisableTiming);
    }

    const int fps_smem = 8193 * 16 + 4097 * 4;   // (sx,sy,sz,sid)[8193] + smd[4097]
    cudaFuncSetAttribute(fps_kernel<0>, cudaFuncAttributeMaxDynamicSharedMemorySize, fps_smem);
    cudaFuncSetAttribute(fps_kernel<1>, cudaFuncAttributeMaxDynamicSharedMemorySize, fps_smem);

    // main stream: weight prep (both branches need g_w0p)
    prep_w0_kernel<<<17, 256>>>(w0);

    // fork
    cudaEventRecord(eFork, 0);
    cudaStreamWaitEvent(sA, eFork, 0);
    cudaStreamWaitEvent(sB, eFork, 0);

    // stream A: transpose -> FPS(attn) -> group(attn sites 0..127)
    transpose_kernel<<<dim3(256, 2, 8), dim3(32, 32), 0, sA>>>(points);
    cudaEventRecord(eT, sA);
    fps_kernel<0><<<BATCH, 1024, fps_smem, sA>>>(xyz, attention, out);
    group_mlp_kernel<0, 128><<<BATCH * 128, 256, 0, sA>>>(xyz, b0, w1, b1, w2, b2, out);

    // stream B: FPS(none) || A ; wait transpose; group(none sites 128..511)
    fps_kernel<1><<<BATCH, 1024, fps_smem, sB>>>(xyz, attention, out);
    cudaStreamWaitEvent(sB, eT, 0);
    group_mlp_kernel<128, 384><<<BATCH * 384, 256, 0, sB>>>(xyz, b0, w1, b1, w2, b2, out);

    // join
    cudaEventRecord(eA, sA);
    cudaEventRecord(eB, sB);
    cudaStreamWaitEvent(0, eA, 0);
    cudaStreamWaitEvent(0, eB, 0);
}

// round 8
// speedup vs baseline: 1.1855x; 1.0599x over previous
#include <cuda_runtime.h>

#define NPTS   8192
#define BATCH  8
#define S_ALL  512
#define K_ATTN 128
#define K_NONE 384
#define DF     64

// ---------------- scratch (static device arrays; no allocation) ----------------
__device__ float g_pts_t[BATCH * NPTS * DF];      // points transposed to [B][N][64]
__device__ float g_new_xyz[BATCH * S_ALL * 3];    // sampled (masked) coords [B][S][3]
__device__ float g_w0p[64 * 68];                  // w0 padded to [64][68]
// FPS chunk-persist state (none branch only)
__device__ float g_cx[BATCH][8193];
__device__ float g_cy[BATCH][8193];
__device__ float g_cz[BATCH][8193];
__device__ int   g_cid[BATCH][8193];
__device__ float g_cmd[BATCH][8448];              // per-slot min-dist
__device__ int   g_state[BATCH][4];               // m, rep, cur

// ---------------- tiny prep: pad w0 rows 67 -> 68 ----------------
__global__ void prep_w0_kernel(const float* __restrict__ w0) {
    int i = blockIdx.x * 256 + threadIdx.x;
    if (i < 64 * 68) {
        int r = i / 68, c = i % 68;
        g_w0p[i] = (c < 67) ? w0[r * 67 + c] : 0.0f;
    }
}

// ---------------- transpose points [B,64,N] -> [B,N,64] ----------------
__global__ void transpose_kernel(const float* __restrict__ points) {
    __shared__ float tile[32][33];
    int b  = blockIdx.z;
    int c0 = blockIdx.y * 32;
    int n0 = blockIdx.x * 32;
    int tx = threadIdx.x, ty = threadIdx.y;
    tile[ty][tx] = points[(b * DF + c0 + ty) * NPTS + n0 + tx];
    __syncthreads();
    g_pts_t[(b * NPTS + n0 + ty) * DF + c0 + tx] = tile[tx][ty];
}

// ---------------- FPS with origin-duplicate compression, chunked [k0,k1) ----------------
// branch 0: attn*xyz, K=128 -> s in [0,128); branch 1: (1-attn)*xyz, K=384 -> s in [128,512)
// k0==0: init+compress (and persist compressed arrays if k1<K). k0>0: restore state.
template <int BRANCH>
__global__ __launch_bounds__(1024) void fps_kernel(
    const float* __restrict__ xyz, const float* __restrict__ attention,
    float* __restrict__ out, int k0, int k1)
{
    extern __shared__ float dsm[];
    float* sx  = dsm;                    // [8193]
    float* sy  = sx + 8193;
    float* sz  = sy + 8193;
    int*   sid = (int*)(sz + 8193);      // [8193]
    float* smd = (float*)(sid + 8193);   // [4097] overflow min-dist (slots >= 4096)

    __shared__ unsigned sscan[32];
    __shared__ unsigned long long sred[2][32];
    __shared__ int srep;

    int b = blockIdx.x;
    const int K     = BRANCH ? K_NONE : K_ATTN;
    const int s_off = BRANCH ? K_ATTN : 0;
    int t = threadIdx.x;
    int wid = t >> 5, lane = t & 31;

    const float* xb = xyz + (size_t)b * 3 * NPTS;
    const float* ab = attention + (size_t)b * NPTS;

    int m, rep, cur;
    float px[4], py[4], pz[4], md[4];

    if (k0 == 0) {
        // ---------- init + compress ----------
        if (t == 0) srep = 0x7FFFFFFF;

        int n0 = t * 8;
        float X[8], Y[8], Z[8], W[8];
        {
            const float4* p = (const float4*)(xb + n0);
            float4 v0 = p[0], v1 = p[1];
            X[0]=v0.x; X[1]=v0.y; X[2]=v0.z; X[3]=v0.w; X[4]=v1.x; X[5]=v1.y; X[6]=v1.z; X[7]=v1.w;
            p = (const float4*)(xb + NPTS + n0);
            v0 = p[0]; v1 = p[1];
            Y[0]=v0.x; Y[1]=v0.y; Y[2]=v0.z; Y[3]=v0.w; Y[4]=v1.x; Y[5]=v1.y; Y[6]=v1.z; Y[7]=v1.w;
            p = (const float4*)(xb + 2 * NPTS + n0);
            v0 = p[0]; v1 = p[1];
            Z[0]=v0.x; Z[1]=v0.y; Z[2]=v0.z; Z[3]=v0.w; Z[4]=v1.x; Z[5]=v1.y; Z[6]=v1.z; Z[7]=v1.w;
            p = (const float4*)(ab + n0);
            v0 = p[0]; v1 = p[1];
            W[0]=v0.x; W[1]=v0.y; W[2]=v0.z; W[3]=v0.w; W[4]=v1.x; W[5]=v1.y; W[6]=v1.z; W[7]=v1.w;
        }
        int myrep = 0x7FFFFFFF;
        #pragma unroll
        for (int j = 0; j < 8; j++) {
            float a = W[j];
            float w = BRANCH ? __fsub_rn(1.0f, a) : a;   // exact: a in {0,1}
            W[j] = w;
            X[j] = __fmul_rn(w, X[j]);
            Y[j] = __fmul_rn(w, Y[j]);
            Z[j] = __fmul_rn(w, Z[j]);
            if (w == 0.0f && (n0 + j) < myrep) myrep = n0 + j;
        }
        __syncthreads();
        if (myrep != 0x7FFFFFFF) atomicMin(&srep, myrep);
        __syncthreads();
        rep = srep;

        unsigned cnt = 0, kmask = 0;
        #pragma unroll
        for (int j = 0; j < 8; j++) {
            bool kp = (W[j] != 0.0f) || ((n0 + j) == rep);
            if (kp) { kmask |= (1u << j); cnt++; }
        }
        unsigned inc = cnt;
        #pragma unroll
        for (int off = 1; off < 32; off <<= 1) {
            unsigned v = __shfl_up_sync(0xffffffffu, inc, off);
            if (lane >= off) inc += v;
        }
        if (lane == 31) sscan[wid] = inc;
        __syncthreads();
        if (wid == 0) {
            unsigned v = sscan[lane];
            #pragma unroll
            for (int off = 1; off < 32; off <<= 1) {
                unsigned u = __shfl_up_sync(0xffffffffu, v, off);
                if (lane >= off) v += u;
            }
            sscan[lane] = v;
        }
        __syncthreads();
        m = (int)sscan[31];
        int o = (int)((wid ? sscan[wid - 1] : 0u) + (inc - cnt));
        #pragma unroll
        for (int j = 0; j < 8; j++) {
            if ((kmask >> j) & 1u) {
                sx[o] = X[j]; sy[o] = Y[j]; sz[o] = Z[j]; sid[o] = n0 + j;
                o++;
            }
        }
        for (int s2 = t; s2 < 4097; s2 += 1024) smd[s2] = 1e10f;
        __syncthreads();

        #pragma unroll
        for (int j = 0; j < 4; j++) {
            int sl = t + j * 1024;
            bool v = sl < m;
            px[j] = v ? sx[sl] : 0.0f;
            py[j] = v ? sy[sl] : 0.0f;
            pz[j] = v ? sz[sl] : 0.0f;
            md[j] = v ? 1e10f : 0.0f;
        }
        cur = 0;

        // persist compressed arrays for later chunks
        if (k1 < K) {
            for (int sl = t; sl < m; sl += 1024) {
                g_cx[b][sl] = sx[sl]; g_cy[b][sl] = sy[sl];
                g_cz[b][sl] = sz[sl]; g_cid[b][sl] = sid[sl];
            }
            if (t == 0) { g_state[b][0] = m; g_state[b][1] = rep; }
        }
    } else {
        // ---------- restore ----------
        m   = g_state[b][0];
        rep = g_state[b][1];
        cur = g_state[b][2];
        for (int sl = t; sl < m; sl += 1024) {
            sx[sl] = g_cx[b][sl]; sy[sl] = g_cy[b][sl];
            sz[sl] = g_cz[b][sl]; sid[sl] = g_cid[b][sl];
        }
        #pragma unroll
        for (int j = 0; j < 4; j++) md[j] = g_cmd[b][t + j * 1024];
        for (int sl = 4096 + t; sl < m; sl += 1024) smd[sl - 4096] = g_cmd[b][sl];
        __syncthreads();
        #pragma unroll
        for (int j = 0; j < 4; j++) {
            int sl = t + j * 1024;
            px[j] = 0.0f; py[j] = 0.0f; pz[j] = 0.0f;
            if (sl < m) { px[j] = sx[sl]; py[j] = sy[sl]; pz[j] = sz[sl]; }
        }
    }

    float* out_xyz  = out;                                           // [B,3,512]
    float* out_attn = out + BATCH * 3 * S_ALL + BATCH * 128 * S_ALL; // [B,1,512]

    for (int k = k0; k < k1; k++) {
        float bx = sx[cur], by = sy[cur], bz = sz[cur];
        if (t == 0) {
            int s = s_off + k;
            out_xyz[(b * 3 + 0) * S_ALL + s] = bx;
            out_xyz[(b * 3 + 1) * S_ALL + s] = by;
            out_xyz[(b * 3 + 2) * S_ALL + s] = bz;
            g_new_xyz[(b * S_ALL + s) * 3 + 0] = bx;
            g_new_xyz[(b * S_ALL + s) * 3 + 1] = by;
            g_new_xyz[(b * S_ALL + s) * 3 + 2] = bz;
            int orig = sid[cur];
            float att = BRANCH ? ((orig == rep) ? 1.0f : 0.0f)
                               : ((orig == rep) ? 0.0f : 1.0f);
            out_attn[b * S_ALL + s] = att;
        }
        if (k == K - 1) break;

        unsigned long long bk = 0ull;
        #pragma unroll
        for (int j = 0; j < 4; j++) {
            float dx = __fsub_rn(px[j], bx);
            float dy = __fsub_rn(py[j], by);
            float dz = __fsub_rn(pz[j], bz);
            float d2 = __fadd_rn(__fadd_rn(__fmul_rn(dx, dx), __fmul_rn(dy, dy)),
                                 __fmul_rn(dz, dz));
            float mn = fminf(md[j], d2);
            md[j] = mn;
            int sl = t + j * 1024;
            unsigned long long key =
                ((unsigned long long)__float_as_uint(mn) << 32) |
                (unsigned long long)(0xFFFFFFFFu - (unsigned)sl);
            if (key > bk) bk = key;
        }
        for (int sl = 4096 + t; sl < m; sl += 1024) {
            float dx = __fsub_rn(sx[sl], bx);
            float dy = __fsub_rn(sy[sl], by);
            float dz = __fsub_rn(sz[sl], bz);
            float d2 = __fadd_rn(__fadd_rn(__fmul_rn(dx, dx), __fmul_rn(dy, dy)),
                                 __fmul_rn(dz, dz));
            float mn = fminf(smd[sl - 4096], d2);
            smd[sl - 4096] = mn;
            unsigned long long key =
                ((unsigned long long)__float_as_uint(mn) << 32) |
                (unsigned long long)(0xFFFFFFFFu - (unsigned)sl);
            if (key > bk) bk = key;
        }
        unsigned vb   = (unsigned)(bk >> 32);
        unsigned vmax = __reduce_max_sync(0xffffffffu, vb);
        unsigned lo   = (vb == vmax) ? (unsigned)bk : 0u;
        unsigned lmax = __reduce_max_sync(0xffffffffu, lo);
        if (lane == 0) sred[k & 1][wid] = ((unsigned long long)vmax << 32) | lmax;
        __syncthreads();
        unsigned long long e = sred[k & 1][lane];
        vb   = (unsigned)(e >> 32);
        vmax = __reduce_max_sync(0xffffffffu, vb);
        lo   = (vb == vmax) ? (unsigned)e : 0u;
        lmax = __reduce_max_sync(0xffffffffu, lo);
        cur  = (int)(0xFFFFFFFFu - lmax);
    }

    // ---------- persist md/cur for next chunk ----------
    if (k1 < K) {
        #pragma unroll
        for (int j = 0; j < 4; j++) g_cmd[b][t + j * 1024] = md[j];
        for (int sl = 4096 + t; sl < m; sl += 1024) g_cmd[b][sl] = smd[sl - 4096];
        if (t == 0) g_state[b][2] = cur;
    }
}

// ================= ball query + grouping + MLP + maxpool: one CTA per (b,s) =================
template <int S_BASE, int NS>
__global__ __launch_bounds__(256, 4) void group_mlp_kernel(
    const float* __restrict__ xyz,
    const float* __restrict__ b0,
    const float* __restrict__ w1, const float* __restrict__ b1,
    const float* __restrict__ w2, const float* __restrict__ b2,
    float* __restrict__ out)
{
    __shared__ __align__(16) float sfeat[68 * 64];   // [c][k], reused as h2
    __shared__ __align__(16) float sh1[64 * 64];     // [c][k]
    __shared__ int sidx[64];
    __shared__ int swarp[8];

    int t = threadIdx.x;
    int wid = t >> 5, lane = t & 31;
    unsigned lmaskb = (1u << lane) - 1u;

    int bs = blockIdx.x;
    int b = bs / NS;
    int s = S_BASE + (bs - b * NS);

    const float* xb = xyz + (size_t)b * 3 * NPTS;
    float qx = g_new_xyz[(b * S_ALL + s) * 3 + 0];
    float qy = g_new_xyz[(b * S_ALL + s) * 3 + 1];
    float qz = g_new_xyz[(b * S_ALL + s) * 3 + 2];
    const float R2 = (float)(0.4 * 0.4);

    if (t < 64) { sidx[t] = -1; sfeat[67 * 64 + t] = 0.0f; }
    __syncthreads();

    // ---- ball query ----
    int total = 0;
    for (int mm = 0; mm < 32; mm++) {
        int n = mm * 256 + t;
        float dx = __fsub_rn(qx, xb[n]);
        float dy = __fsub_rn(qy, xb[NPTS + n]);
        float dz = __fsub_rn(qz, xb[2 * NPTS + n]);
        float d2 = __fadd_rn(__fadd_rn(__fmul_rn(dx, dx), __fmul_rn(dy, dy)),
                             __fmul_rn(dz, dz));
        bool pred = d2 < R2;
        unsigned ball = __ballot_sync(0xffffffffu, pred);
        if (lane == 0) swarp[wid] = __popc(ball);
        __syncthreads();
        int off = total, all = 0;
        #pragma unroll
        for (int w = 0; w < 8; w++) {
            int v = swarp[w];
            all += v;
            if (w < wid) off += v;
        }
        if (pred) {
            int slot = off + __popc(ball & lmaskb);
            if (slot < 64) sidx[slot] = n;
        }
        total += all;
        __syncthreads();
        if (total >= 64) break;
    }

    // ---- feat [68][64] ----
    if (t < 192) {
        int c = t >> 6, kk = t & 63;
        int idx = sidx[kk];
        float q = (c == 0) ? qx : ((c == 1) ? qy : qz);
        float g = (idx >= 0) ? xb[c * NPTS + idx] : 0.0f;
        sfeat[c * 64 + kk] = __fsub_rn(g, q);
    }
    {
        int kk = t & 63, fq = t >> 6;
        int idx = sidx[kk];
        int gi = (idx >= 0) ? idx : (NPTS - 1);
        const float4* row = (const float4*)(g_pts_t + ((size_t)b * NPTS + gi) * DF);
        #pragma unroll
        for (int f2 = 0; f2 < 4; f2++) {
            int f = fq * 4 + f2;
            float4 v = row[f];
            sfeat[(3 + 4 * f + 0) * 64 + kk] = v.x;
            sfeat[(3 + 4 * f + 1) * 64 + kk] = v.y;
            sfeat[(3 + 4 * f + 2) * 64 + kk] = v.z;
            sfeat[(3 + 4 * f + 3) * 64 + kk] = v.w;
        }
    }
    __syncthreads();

    int og = t >> 4;              // 0..15
    int kb = (t & 15) * 4;        // 0..60

    // ---- layer1: 68(pad) -> 64, relu ----
    {
        const float4* w0p = (const float4*)g_w0p + og * 68;  // 4 rows of 17 float4
        const float*  fp  = sfeat + kb;
        float acc[4][4];
        #pragma unroll
        for (int i = 0; i < 4; i++) {
            float bv = __ldg(&b0[og * 4 + i]);
            acc[i][0] = acc[i][1] = acc[i][2] = acc[i][3] = bv;
        }
        #pragma unroll
        for (int c4 = 0; c4 < 17; c4++) {
            float4 f0 = *(const float4*)(fp + (c4 * 4 + 0) * 64);
            float4 f1 = *(const float4*)(fp + (c4 * 4 + 1) * 64);
            float4 f2 = *(const float4*)(fp + (c4 * 4 + 2) * 64);
            float4 f3 = *(const float4*)(fp + (c4 * 4 + 3) * 64);
            #pragma unroll
            for (int i = 0; i < 4; i++) {
                float4 w = __ldg(&w0p[i * 17 + c4]);
                acc[i][0] = fmaf(w.x, f0.x, acc[i][0]); acc[i][0] = fmaf(w.y, f1.x, acc[i][0]);
                acc[i][0] = fmaf(w.z, f2.x, acc[i][0]); acc[i][0] = fmaf(w.w, f3.x, acc[i][0]);
                acc[i][1] = fmaf(w.x, f0.y, acc[i][1]); acc[i][1] = fmaf(w.y, f1.y, acc[i][1]);
                acc[i][1] = fmaf(w.z, f2.y, acc[i][1]); acc[i][1] = fmaf(w.w, f3.y, acc[i][1]);
                acc[i][2] = fmaf(w.x, f0.z, acc[i][2]); acc[i][2] = fmaf(w.y, f1.z, acc[i][2]);
                acc[i][2] = fmaf(w.z, f2.z, acc[i][2]); acc[i][2] = fmaf(w.w, f3.z, acc[i][2]);
                acc[i][3] = fmaf(w.x, f0.w, acc[i][3]); acc[i][3] = fmaf(w.y, f1.w, acc[i][3]);
                acc[i][3] = fmaf(w.z, f2.w, acc[i][3]); acc[i][3] = fmaf(w.w, f3.w, acc[i][3]);
            }
        }
        #pragma unroll
        for (int i = 0; i < 4; i++) {
            float4 r;
            r.x = fmaxf(acc[i][0], 0.f); r.y = fmaxf(acc[i][1], 0.f);
            r.z = fmaxf(acc[i][2], 0.f); r.w = fmaxf(acc[i][3], 0.f);
            *(float4*)(sh1 + (og * 4 + i) * 64 + kb) = r;
        }
    }
    __syncthreads();

    // ---- layer2: 64 -> 64, relu ----
    {
        const float4* w1p = (const float4*)w1 + og * 64;
        const float*  fp  = sh1 + kb;
        float acc[4][4];
        #pragma unroll
        for (int i = 0; i < 4; i++) {
            float bv = __ldg(&b1[og * 4 + i]);
            acc[i][0] = acc[i][1] = acc[i][2] = acc[i][3] = bv;
        }
        #pragma unroll
        for (int c4 = 0; c4 < 16; c4++) {
            float4 f0 = *(const float4*)(fp + (c4 * 4 + 0) * 64);
            float4 f1 = *(const float4*)(fp + (c4 * 4 + 1) * 64);
            float4 f2 = *(const float4*)(fp + (c4 * 4 + 2) * 64);
            float4 f3 = *(const float4*)(fp + (c4 * 4 + 3) * 64);
            #pragma unroll
            for (int i = 0; i < 4; i++) {
                float4 w = __ldg(&w1p[i * 16 + c4]);
                acc[i][0] = fmaf(w.x, f0.x, acc[i][0]); acc[i][0] = fmaf(w.y, f1.x, acc[i][0]);
                acc[i][0] = fmaf(w.z, f2.x, acc[i][0]); acc[i][0] = fmaf(w.w, f3.x, acc[i][0]);
                acc[i][1] = fmaf(w.x, f0.y, acc[i][1]); acc[i][1] = fmaf(w.y, f1.y, acc[i][1]);
                acc[i][1] = fmaf(w.z, f2.y, acc[i][1]); acc[i][1] = fmaf(w.w, f3.y, acc[i][1]);
                acc[i][2] = fmaf(w.x, f0.z, acc[i][2]); acc[i][2] = fmaf(w.y, f1.z, acc[i][2]);
                acc[i][2] = fmaf(w.z, f2.z, acc[i][2]); acc[i][2] = fmaf(w.w, f3.z, acc[i][2]);
                acc[i][3] = fmaf(w.x, f0.w, acc[i][3]); acc[i][3] = fmaf(w.y, f1.w, acc[i][3]);
                acc[i][3] = fmaf(w.z, f2.w, acc[i][3]); acc[i][3] = fmaf(w.w, f3.w, acc[i][3]);
            }
        }
        __syncthreads();
        #pragma unroll
        for (int i = 0; i < 4; i++) {
            float4 r;
            r.x = fmaxf(acc[i][0], 0.f); r.y = fmaxf(acc[i][1], 0.f);
            r.z = fmaxf(acc[i][2], 0.f); r.w = fmaxf(acc[i][3], 0.f);
            *(float4*)(sfeat + (og * 4 + i) * 64 + kb) = r;
        }
    }
    __syncthreads();

    // ---- layer3: 64 -> 128, relu + maxpool; two passes of 64 outputs ----
    {
        float* out_points = out + BATCH * 3 * S_ALL;   // [B,128,512]
        const float* fp = sfeat + kb;
        #pragma unroll 1
        for (int h = 0; h < 2; h++) {
            const float4* w2p = (const float4*)w2 + (h * 64 + og * 4) * 16;
            float acc[4][4];
            #pragma unroll
            for (int i = 0; i < 4; i++) {
                float bv = __ldg(&b2[h * 64 + og * 4 + i]);
                acc[i][0] = acc[i][1] = acc[i][2] = acc[i][3] = bv;
            }
            #pragma unroll
            for (int c4 = 0; c4 < 16; c4++) {
                float4 f0 = *(const float4*)(fp + (c4 * 4 + 0) * 64);
                float4 f1 = *(const float4*)(fp + (c4 * 4 + 1) * 64);
                float4 f2 = *(const float4*)(fp + (c4 * 4 + 2) * 64);
                float4 f3 = *(const float4*)(fp + (c4 * 4 + 3) * 64);
                #pragma unroll
                for (int i = 0; i < 4; i++) {
                    float4 w = __ldg(&w2p[i * 16 + c4]);
                    acc[i][0] = fmaf(w.x, f0.x, acc[i][0]); acc[i][0] = fmaf(w.y, f1.x, acc[i][0]);
                    acc[i][0] = fmaf(w.z, f2.x, acc[i][0]); acc[i][0] = fmaf(w.w, f3.x, acc[i][0]);
                    acc[i][1] = fmaf(w.x, f0.y, acc[i][1]); acc[i][1] = fmaf(w.y, f1.y, acc[i][1]);
                    acc[i][1] = fmaf(w.z, f2.y, acc[i][1]); acc[i][1] = fmaf(w.w, f3.y, acc[i][1]);
                    acc[i][2] = fmaf(w.x, f0.z, acc[i][2]); acc[i][2] = fmaf(w.y, f1.z, acc[i][2]);
                    acc[i][2] = fmaf(w.z, f2.z, acc[i][2]); acc[i][2] = fmaf(w.w, f3.z, acc[i][2]);
                    acc[i][3] = fmaf(w.x, f0.w, acc[i][3]); acc[i][3] = fmaf(w.y, f1.w, acc[i][3]);
                    acc[i][3] = fmaf(w.z, f2.w, acc[i][3]); acc[i][3] = fmaf(w.w, f3.w, acc[i][3]);
                }
            }
            #pragma unroll
            for (int i = 0; i < 4; i++) {
                float mv = fmaxf(fmaxf(acc[i][0], acc[i][1]), fmaxf(acc[i][2], acc[i][3]));
                #pragma unroll
                for (int off = 1; off < 16; off <<= 1)
                    mv = fmaxf(mv, __shfl_xor_sync(0xffffffffu, mv, off));
                if ((t & 15) == 0)
                    out_points[((size_t)b * 128 + h * 64 + og * 4 + i) * S_ALL + s] = fmaxf(mv, 0.0f);
            }
        }
    }
}

extern "C" void kernel_launch(void* const* d_in, const int* in_sizes, int n_in,
                              void* d_out, int out_size) {
    const float* xyz       = (const float*)d_in[0];
    const float* points    = (const float*)d_in[1];
    const float* attention = (const float*)d_in[2];
    const float* w0 = (const float*)d_in[3];
    const float* b0 = (const float*)d_in[4];
    const float* w1 = (const float*)d_in[5];
    const float* b1 = (const float*)d_in[6];
    const float* w2 = (const float*)d_in[7];
    const float* b2 = (const float*)d_in[8];
    float* out = (float*)d_out;

    // one-time stream/event infra
    static cudaStream_t sA = nullptr, sB = nullptr, sD = nullptr;
    static cudaEvent_t eFork = nullptr, eT = nullptr, eA = nullptr, eD = nullptr;
    static cudaEvent_t eN[4] = {nullptr, nullptr, nullptr, nullptr};
    if (sA == nullptr) {
        cudaStreamCreateWithFlags(&sA, cudaStreamNonBlocking);
        cudaStreamCreateWithFlags(&sB, cudaStreamNonBlocking);
        cudaStreamCreateWithFlags(&sD, cudaStreamNonBlocking);
        cudaEventCreateWithFlags(&eFork, cudaEventDisableTiming);
        cudaEventCreateWithFlags(&eT,    cudaEventDisableTiming);
        cudaEventCreateWithFlags(&eA,    cudaEventDisableTiming);
        cudaEventCreateWithFlags(&eD,    cudaEventDisableTiming);
        for (int i = 0; i < 4; i++) cudaEventCreateWithFlags(&eN[i], cudaEventDisableTiming);
    }

    const int fps_smem = 8193 * 16 + 4097 * 4;   // (sx,sy,sz,sid)[8193] + smd[4097]
    cudaFuncSetAttribute(fps_kernel<0>, cudaFuncAttributeMaxDynamicSharedMemorySize, fps_smem);
    cudaFuncSetAttribute(fps_kernel<1>, cudaFuncAttributeMaxDynamicSharedMemorySize, fps_smem);

    // main stream: weight prep
    prep_w0_kernel<<<17, 256>>>(w0);

    // fork
    cudaEventRecord(eFork, 0);
    cudaStreamWaitEvent(sA, eFork, 0);
    cudaStreamWaitEvent(sB, eFork, 0);
    cudaStreamWaitEvent(sD, eFork, 0);

    // stream A: transpose -> FPS(attn, single chunk) -> group(attn sites 0..127)
    transpose_kernel<<<dim3(256, 2, 8), dim3(32, 32), 0, sA>>>(points);
    cudaEventRecord(eT, sA);
    fps_kernel<0><<<BATCH, 1024, fps_smem, sA>>>(xyz, attention, out, 0, K_ATTN);
    group_mlp_kernel<0, 128><<<BATCH * 128, 256, 0, sA>>>(xyz, b0, w1, b1, w2, b2, out);
    cudaEventRecord(eA, sA);

    // stream B: FPS(none) in 4 chunks of 96 iterations, event after each
    fps_kernel<1><<<BATCH, 1024, fps_smem, sB>>>(xyz, attention, out, 0, 96);
    cudaEventRecord(eN[0], sB);
    fps_kernel<1><<<BATCH, 1024, fps_smem, sB>>>(xyz, attention, out, 96, 192);
    cudaEventRecord(eN[1], sB);
    fps_kernel<1><<<BATCH, 1024, fps_smem, sB>>>(xyz, attention, out, 192, 288);
    cudaEventRecord(eN[2], sB);
    fps_kernel<1><<<BATCH, 1024, fps_smem, sB>>>(xyz, attention, out, 288, 384);
    cudaEventRecord(eN[3], sB);

    // stream D: group(none) in 4 site-chunks, each gated on its FPS chunk (+transpose)
    cudaStreamWaitEvent(sD, eT, 0);
    cudaStreamWaitEvent(sD, eN[0], 0);
    group_mlp_kernel<128, 96><<<BATCH * 96, 256, 0, sD>>>(xyz, b0, w1, b1, w2, b2, out);
    cudaStreamWaitEvent(sD, eN[1], 0);
    group_mlp_kernel<224, 96><<<BATCH * 96, 256, 0, sD>>>(xyz, b0, w1, b1, w2, b2, out);
    cudaStreamWaitEvent(sD, eN[2], 0);
    group_mlp_kernel<320, 96><<<BATCH * 96, 256, 0, sD>>>(xyz, b0, w1, b1, w2, b2, out);
    cudaStreamWaitEvent(sD, eN[3], 0);
    group_mlp_kernel<416, 96><<<BATCH * 96, 256, 0, sD>>>(xyz, b0, w1, b1, w2, b2, out);
    cudaEventRecord(eD, sD);

    // join
    cudaStreamWaitEvent(0, eA, 0);
    cudaStreamWaitEvent(0, eD, 0);
}

// round 9
// speedup vs baseline: 1.3080x; 1.1033x over previous
#include <cuda_runtime.h>

#define NPTS   8192
#define BATCH  8
#define S_ALL  512
#define K_ATTN 128
#define K_NONE 384
#define DF     64

typedef unsigned long long ull;

// packed f32x2 helpers (lane-wise IEEE fp32 — bit-identical to scalar fmaf)
#define PACK2(d, s)      asm("mov.b64 %0, {%1, %1};" : "=l"(d) : "f"(s))
#define UNPACK2(lo, hi, s) asm("mov.b64 {%0, %1}, %2;" : "=f"(lo), "=f"(hi) : "l"(s))
#define FMA2(d, a, b, c) asm("fma.rn.f32x2 %0, %1, %2, %3;" : "=l"(d) : "l"(a), "l"(b), "l"(c))

// ---------------- scratch (static device arrays; no allocation) ----------------
__device__ float g_pts_t[BATCH * NPTS * DF];      // points transposed to [B][N][64]
__device__ float g_new_xyz[BATCH * S_ALL * 3];    // sampled (masked) coords [B][S][3]
__device__ float g_w0p[64 * 68];                  // w0 padded to [64][68]
// FPS chunk-persist state (none branch only)
__device__ float g_cx[BATCH][8193];
__device__ float g_cy[BATCH][8193];
__device__ float g_cz[BATCH][8193];
__device__ int   g_cid[BATCH][8193];
__device__ float g_cmd[BATCH][8448];              // per-slot min-dist
__device__ int   g_state[BATCH][4];               // m, rep, cur

// ---------------- tiny prep: pad w0 rows 67 -> 68 ----------------
__global__ void prep_w0_kernel(const float* __restrict__ w0) {
    int i = blockIdx.x * 256 + threadIdx.x;
    if (i < 64 * 68) {
        int r = i / 68, c = i % 68;
        g_w0p[i] = (c < 67) ? w0[r * 67 + c] : 0.0f;
    }
}

// ---------------- transpose points [B,64,N] -> [B,N,64] ----------------
__global__ void transpose_kernel(const float* __restrict__ points) {
    __shared__ float tile[32][33];
    int b  = blockIdx.z;
    int c0 = blockIdx.y * 32;
    int n0 = blockIdx.x * 32;
    int tx = threadIdx.x, ty = threadIdx.y;
    tile[ty][tx] = points[(b * DF + c0 + ty) * NPTS + n0 + tx];
    __syncthreads();
    g_pts_t[(b * NPTS + n0 + ty) * DF + c0 + tx] = tile[tx][ty];
}

// ---------------- FPS with origin-duplicate compression, chunked [k0,k1) ----------------
template <int BRANCH>
__global__ __launch_bounds__(1024) void fps_kernel(
    const float* __restrict__ xyz, const float* __restrict__ attention,
    float* __restrict__ out, int k0, int k1)
{
    extern __shared__ float dsm[];
    float* sx  = dsm;                    // [8193]
    float* sy  = sx + 8193;
    float* sz  = sy + 8193;
    int*   sid = (int*)(sz + 8193);      // [8193]
    float* smd = (float*)(sid + 8193);   // [4097] overflow min-dist

    __shared__ unsigned sscan[32];
    __shared__ unsigned long long sred[2][32];
    __shared__ int srep;

    int b = blockIdx.x;
    const int K     = BRANCH ? K_NONE : K_ATTN;
    const int s_off = BRANCH ? K_ATTN : 0;
    int t = threadIdx.x;
    int wid = t >> 5, lane = t & 31;

    const float* xb = xyz + (size_t)b * 3 * NPTS;
    const float* ab = attention + (size_t)b * NPTS;

    int m, rep, cur;
    float px[4], py[4], pz[4], md[4];

    if (k0 == 0) {
        if (t == 0) srep = 0x7FFFFFFF;

        int n0 = t * 8;
        float X[8], Y[8], Z[8], W[8];
        {
            const float4* p = (const float4*)(xb + n0);
            float4 v0 = p[0], v1 = p[1];
            X[0]=v0.x; X[1]=v0.y; X[2]=v0.z; X[3]=v0.w; X[4]=v1.x; X[5]=v1.y; X[6]=v1.z; X[7]=v1.w;
            p = (const float4*)(xb + NPTS + n0);
            v0 = p[0]; v1 = p[1];
            Y[0]=v0.x; Y[1]=v0.y; Y[2]=v0.z; Y[3]=v0.w; Y[4]=v1.x; Y[5]=v1.y; Y[6]=v1.z; Y[7]=v1.w;
            p = (const float4*)(xb + 2 * NPTS + n0);
            v0 = p[0]; v1 = p[1];
            Z[0]=v0.x; Z[1]=v0.y; Z[2]=v0.z; Z[3]=v0.w; Z[4]=v1.x; Z[5]=v1.y; Z[6]=v1.z; Z[7]=v1.w;
            p = (const float4*)(ab + n0);
            v0 = p[0]; v1 = p[1];
            W[0]=v0.x; W[1]=v0.y; W[2]=v0.z; W[3]=v0.w; W[4]=v1.x; W[5]=v1.y; W[6]=v1.z; W[7]=v1.w;
        }
        int myrep = 0x7FFFFFFF;
        #pragma unroll
        for (int j = 0; j < 8; j++) {
            float a = W[j];
            float w = BRANCH ? __fsub_rn(1.0f, a) : a;   // exact: a in {0,1}
            W[j] = w;
            X[j] = __fmul_rn(w, X[j]);
            Y[j] = __fmul_rn(w, Y[j]);
            Z[j] = __fmul_rn(w, Z[j]);
            if (w == 0.0f && (n0 + j) < myrep) myrep = n0 + j;
        }
        __syncthreads();
        if (myrep != 0x7FFFFFFF) atomicMin(&srep, myrep);
        __syncthreads();
        rep = srep;

        unsigned cnt = 0, kmask = 0;
        #pragma unroll
        for (int j = 0; j < 8; j++) {
            bool kp = (W[j] != 0.0f) || ((n0 + j) == rep);
            if (kp) { kmask |= (1u << j); cnt++; }
        }
        unsigned inc = cnt;
        #pragma unroll
        for (int off = 1; off < 32; off <<= 1) {
            unsigned v = __shfl_up_sync(0xffffffffu, inc, off);
            if (lane >= off) inc += v;
        }
        if (lane == 31) sscan[wid] = inc;
        __syncthreads();
        if (wid == 0) {
            unsigned v = sscan[lane];
            #pragma unroll
            for (int off = 1; off < 32; off <<= 1) {
                unsigned u = __shfl_up_sync(0xffffffffu, v, off);
                if (lane >= off) v += u;
            }
            sscan[lane] = v;
        }
        __syncthreads();
        m = (int)sscan[31];
        int o = (int)((wid ? sscan[wid - 1] : 0u) + (inc - cnt));
        #pragma unroll
        for (int j = 0; j < 8; j++) {
            if ((kmask >> j) & 1u) {
                sx[o] = X[j]; sy[o] = Y[j]; sz[o] = Z[j]; sid[o] = n0 + j;
                o++;
            }
        }
        for (int s2 = t; s2 < 4097; s2 += 1024) smd[s2] = 1e10f;
        __syncthreads();

        #pragma unroll
        for (int j = 0; j < 4; j++) {
            int sl = t + j * 1024;
            bool v = sl < m;
            px[j] = v ? sx[sl] : 0.0f;
            py[j] = v ? sy[sl] : 0.0f;
            pz[j] = v ? sz[sl] : 0.0f;
            md[j] = v ? 1e10f : 0.0f;
        }
        cur = 0;

        if (k1 < K) {
            for (int sl = t; sl < m; sl += 1024) {
                g_cx[b][sl] = sx[sl]; g_cy[b][sl] = sy[sl];
                g_cz[b][sl] = sz[sl]; g_cid[b][sl] = sid[sl];
            }
            if (t == 0) { g_state[b][0] = m; g_state[b][1] = rep; }
        }
    } else {
        m   = g_state[b][0];
        rep = g_state[b][1];
        cur = g_state[b][2];
        for (int sl = t; sl < m; sl += 1024) {
            sx[sl] = g_cx[b][sl]; sy[sl] = g_cy[b][sl];
            sz[sl] = g_cz[b][sl]; sid[sl] = g_cid[b][sl];
        }
        #pragma unroll
        for (int j = 0; j < 4; j++) md[j] = g_cmd[b][t + j * 1024];
        for (int sl = 4096 + t; sl < m; sl += 1024) smd[sl - 4096] = g_cmd[b][sl];
        __syncthreads();
        #pragma unroll
        for (int j = 0; j < 4; j++) {
            int sl = t + j * 1024;
            px[j] = 0.0f; py[j] = 0.0f; pz[j] = 0.0f;
            if (sl < m) { px[j] = sx[sl]; py[j] = sy[sl]; pz[j] = sz[sl]; }
        }
    }

    float* out_xyz  = out;                                           // [B,3,512]
    float* out_attn = out + BATCH * 3 * S_ALL + BATCH * 128 * S_ALL; // [B,1,512]

    for (int k = k0; k < k1; k++) {
        float bx = sx[cur], by = sy[cur], bz = sz[cur];
        if (t == 0) {
            int s = s_off + k;
            out_xyz[(b * 3 + 0) * S_ALL + s] = bx;
            out_xyz[(b * 3 + 1) * S_ALL + s] = by;
            out_xyz[(b * 3 + 2) * S_ALL + s] = bz;
            g_new_xyz[(b * S_ALL + s) * 3 + 0] = bx;
            g_new_xyz[(b * S_ALL + s) * 3 + 1] = by;
            g_new_xyz[(b * S_ALL + s) * 3 + 2] = bz;
            int orig = sid[cur];
            float att = BRANCH ? ((orig == rep) ? 1.0f : 0.0f)
                               : ((orig == rep) ? 0.0f : 1.0f);
            out_attn[b * S_ALL + s] = att;
        }
        if (k == K - 1) break;

        unsigned long long bk = 0ull;
        #pragma unroll
        for (int j = 0; j < 4; j++) {
            float dx = __fsub_rn(px[j], bx);
            float dy = __fsub_rn(py[j], by);
            float dz = __fsub_rn(pz[j], bz);
            float d2 = __fadd_rn(__fadd_rn(__fmul_rn(dx, dx), __fmul_rn(dy, dy)),
                                 __fmul_rn(dz, dz));
            float mn = fminf(md[j], d2);
            md[j] = mn;
            int sl = t + j * 1024;
            unsigned long long key =
                ((unsigned long long)__float_as_uint(mn) << 32) |
                (unsigned long long)(0xFFFFFFFFu - (unsigned)sl);
            if (key > bk) bk = key;
        }
        for (int sl = 4096 + t; sl < m; sl += 1024) {
            float dx = __fsub_rn(sx[sl], bx);
            float dy = __fsub_rn(sy[sl], by);
            float dz = __fsub_rn(sz[sl], bz);
            float d2 = __fadd_rn(__fadd_rn(__fmul_rn(dx, dx), __fmul_rn(dy, dy)),
                                 __fmul_rn(dz, dz));
            float mn = fminf(smd[sl - 4096], d2);
            smd[sl - 4096] = mn;
            unsigned long long key =
                ((unsigned long long)__float_as_uint(mn) << 32) |
                (unsigned long long)(0xFFFFFFFFu - (unsigned)sl);
            if (key > bk) bk = key;
        }
        unsigned vb   = (unsigned)(bk >> 32);
        unsigned vmax = __reduce_max_sync(0xffffffffu, vb);
        unsigned lo   = (vb == vmax) ? (unsigned)bk : 0u;
        unsigned lmax = __reduce_max_sync(0xffffffffu, lo);
        if (lane == 0) sred[k & 1][wid] = ((unsigned long long)vmax << 32) | lmax;
        __syncthreads();
        unsigned long long e = sred[k & 1][lane];
        vb   = (unsigned)(e >> 32);
        vmax = __reduce_max_sync(0xffffffffu, vb);
        lo   = (vb == vmax) ? (unsigned)e : 0u;
        lmax = __reduce_max_sync(0xffffffffu, lo);
        cur  = (int)(0xFFFFFFFFu - lmax);
    }

    if (k1 < K) {
        #pragma unroll
        for (int j = 0; j < 4; j++) g_cmd[b][t + j * 1024] = md[j];
        for (int sl = 4096 + t; sl < m; sl += 1024) g_cmd[b][sl] = smd[sl - 4096];
        if (t == 0) g_state[b][2] = cur;
    }
}

// ================= group + MLP + maxpool: 128-thread CTA per (b,s), Mr=8/Nr=4, f32x2 =================
// Feature redundancy halved (2 og rows share lanes per warp... og groups of 16 lanes, 8 rows each).
// Layer outputs staged fully in registers before overwriting sfeat -> no sh1 buffer (smem ~18KB).
template <int S_BASE, int NS>
__global__ __launch_bounds__(128, 7) void group_mlp_kernel(
    const float* __restrict__ xyz,
    const float* __restrict__ b0,
    const float* __restrict__ w1, const float* __restrict__ b1,
    const float* __restrict__ w2, const float* __restrict__ b2,
    float* __restrict__ out)
{
    __shared__ __align__(16) float sfeat[68 * 64];   // [c][k]; rows 0..63 reused for h1, h2
    __shared__ int sidx[64];
    __shared__ int swarp[4];

    int t = threadIdx.x;
    int wid = t >> 5, lane = t & 31;
    unsigned lmaskb = (1u << lane) - 1u;

    int bs = blockIdx.x;
    int b = bs / NS;
    int s = S_BASE + (bs - b * NS);

    const float* xb = xyz + (size_t)b * 3 * NPTS;
    float qx = g_new_xyz[(b * S_ALL + s) * 3 + 0];
    float qy = g_new_xyz[(b * S_ALL + s) * 3 + 1];
    float qz = g_new_xyz[(b * S_ALL + s) * 3 + 2];
    const float R2 = (float)(0.4 * 0.4);

    if (t < 64) { sidx[t] = -1; sfeat[67 * 64 + t] = 0.0f; }
    __syncthreads();

    // ---- ball query: ordered first-64 collection, 64 coalesced rounds (early break) ----
    int total = 0;
    for (int mm = 0; mm < 64; mm++) {
        int n = mm * 128 + t;
        float dx = __fsub_rn(qx, xb[n]);
        float dy = __fsub_rn(qy, xb[NPTS + n]);
        float dz = __fsub_rn(qz, xb[2 * NPTS + n]);
        float d2 = __fadd_rn(__fadd_rn(__fmul_rn(dx, dx), __fmul_rn(dy, dy)),
                             __fmul_rn(dz, dz));
        bool pred = d2 < R2;
        unsigned ball = __ballot_sync(0xffffffffu, pred);
        if (lane == 0) swarp[wid] = __popc(ball);
        __syncthreads();
        int off = total, all = 0;
        #pragma unroll
        for (int w = 0; w < 4; w++) {
            int v = swarp[w];
            all += v;
            if (w < wid) off += v;
        }
        if (pred) {
            int slot = off + __popc(ball & lmaskb);
            if (slot < 64) sidx[slot] = n;
        }
        total += all;
        __syncthreads();
        if (total >= 64) break;
    }

    // ---- feat [68][64] ----
    if (t < 64) {
        int idx = sidx[t];
        float gx = (idx >= 0) ? xb[idx] : 0.0f;
        float gy = (idx >= 0) ? xb[NPTS + idx] : 0.0f;
        float gz = (idx >= 0) ? xb[2 * NPTS + idx] : 0.0f;
        sfeat[0 * 64 + t] = __fsub_rn(gx, qx);
        sfeat[1 * 64 + t] = __fsub_rn(gy, qy);
        sfeat[2 * 64 + t] = __fsub_rn(gz, qz);
    }
    {
        int kk = t & 63, fq = t >> 6;            // 2 threads per sample row, 8 float4 each
        int idx = sidx[kk];
        int gi = (idx >= 0) ? idx : (NPTS - 1);
        const float4* row = (const float4*)(g_pts_t + ((size_t)b * NPTS + gi) * DF);
        #pragma unroll
        for (int f2 = 0; f2 < 8; f2++) {
            int f = fq * 8 + f2;
            float4 v = row[f];
            sfeat[(3 + 4 * f + 0) * 64 + kk] = v.x;
            sfeat[(3 + 4 * f + 1) * 64 + kk] = v.y;
            sfeat[(3 + 4 * f + 2) * 64 + kk] = v.z;
            sfeat[(3 + 4 * f + 3) * 64 + kk] = v.w;
        }
    }
    __syncthreads();

    int og = t >> 4;              // 0..7  (8 output rows each)
    int kb = (t & 15) * 4;        // 0..60 (4 samples -> 2 f32x2 pairs)
    const float* fp = sfeat + kb;

    ull acc[8][2];

    // ---- layer1: 68(pad) -> 64, relu (full output staged in regs, then overwrite sfeat) ----
    {
        const float4* w0p = (const float4*)g_w0p + og * 8 * 17;
        #pragma unroll
        for (int i = 0; i < 8; i++) {
            float bv = __ldg(&b0[og * 8 + i]);
            PACK2(acc[i][0], bv); acc[i][1] = acc[i][0];
        }
        #pragma unroll
        for (int c4 = 0; c4 < 17; c4++) {
            ulonglong2 F0 = *(const ulonglong2*)(fp + (c4 * 4 + 0) * 64);
            ulonglong2 F1 = *(const ulonglong2*)(fp + (c4 * 4 + 1) * 64);
            ulonglong2 F2 = *(const ulonglong2*)(fp + (c4 * 4 + 2) * 64);
            ulonglong2 F3 = *(const ulonglong2*)(fp + (c4 * 4 + 3) * 64);
            #pragma unroll
            for (int i = 0; i < 8; i++) {
                float4 w = __ldg(&w0p[i * 17 + c4]);
                ull wx, wy, wz, ww;
                PACK2(wx, w.x); PACK2(wy, w.y); PACK2(wz, w.z); PACK2(ww, w.w);
                FMA2(acc[i][0], wx, F0.x, acc[i][0]); FMA2(acc[i][1], wx, F0.y, acc[i][1]);
                FMA2(acc[i][0], wy, F1.x, acc[i][0]); FMA2(acc[i][1], wy, F1.y, acc[i][1]);
                FMA2(acc[i][0], wz, F2.x, acc[i][0]); FMA2(acc[i][1], wz, F2.y, acc[i][1]);
                FMA2(acc[i][0], ww, F3.x, acc[i][0]); FMA2(acc[i][1], ww, F3.y, acc[i][1]);
            }
        }
        __syncthreads();   // all layer-1 reads of sfeat complete
        #pragma unroll
        for (int i = 0; i < 8; i++) {
            float a0, a1, a2, a3;
            UNPACK2(a0, a1, acc[i][0]); UNPACK2(a2, a3, acc[i][1]);
            float4 r;
            r.x = fmaxf(a0, 0.f); r.y = fmaxf(a1, 0.f);
            r.z = fmaxf(a2, 0.f); r.w = fmaxf(a3, 0.f);
            *(float4*)(sfeat + (og * 8 + i) * 64 + kb) = r;
        }
    }
    __syncthreads();

    // ---- layer2: 64 -> 64, relu ----
    {
        const float4* w1p = (const float4*)w1 + og * 8 * 16;
        #pragma unroll
        for (int i = 0; i < 8; i++) {
            float bv = __ldg(&b1[og * 8 + i]);
            PACK2(acc[i][0], bv); acc[i][1] = acc[i][0];
        }
        #pragma unroll
        for (int c4 = 0; c4 < 16; c4++) {
            ulonglong2 F0 = *(const ulonglong2*)(fp + (c4 * 4 + 0) * 64);
            ulonglong2 F1 = *(const ulonglong2*)(fp + (c4 * 4 + 1) * 64);
            ulonglong2 F2 = *(const ulonglong2*)(fp + (c4 * 4 + 2) * 64);
            ulonglong2 F3 = *(const ulonglong2*)(fp + (c4 * 4 + 3) * 64);
            #pragma unroll
            for (int i = 0; i < 8; i++) {
                float4 w = __ldg(&w1p[i * 16 + c4]);
                ull wx, wy, wz, ww;
                PACK2(wx, w.x); PACK2(wy, w.y); PACK2(wz, w.z); PACK2(ww, w.w);
                FMA2(acc[i][0], wx, F0.x, acc[i][0]); FMA2(acc[i][1], wx, F0.y, acc[i][1]);
                FMA2(acc[i][0], wy, F1.x, acc[i][0]); FMA2(acc[i][1], wy, F1.y, acc[i][1]);
                FMA2(acc[i][0], wz, F2.x, acc[i][0]); FMA2(acc[i][1], wz, F2.y, acc[i][1]);
                FMA2(acc[i][0], ww, F3.x, acc[i][0]); FMA2(acc[i][1], ww, F3.y, acc[i][1]);
            }
        }
        __syncthreads();   // all layer-2 reads complete before overwrite
        #pragma unroll
        for (int i = 0; i < 8; i++) {
            float a0, a1, a2, a3;
            UNPACK2(a0, a1, acc[i][0]); UNPACK2(a2, a3, acc[i][1]);
            float4 r;
            r.x = fmaxf(a0, 0.f); r.y = fmaxf(a1, 0.f);
            r.z = fmaxf(a2, 0.f); r.w = fmaxf(a3, 0.f);
            *(float4*)(sfeat + (og * 8 + i) * 64 + kb) = r;
        }
    }
    __syncthreads();

    // ---- layer3: 64 -> 128, relu + maxpool; two passes of 64 outputs ----
    {
        float* out_points = out + BATCH * 3 * S_ALL;   // [B,128,512]
        #pragma unroll 1
        for (int h = 0; h < 2; h++) {
            const float4* w2p = (const float4*)w2 + (h * 64 + og * 8) * 16;
            #pragma unroll
            for (int i = 0; i < 8; i++) {
                float bv = __ldg(&b2[h * 64 + og * 8 + i]);
                PACK2(acc[i][0], bv); acc[i][1] = acc[i][0];
            }
            #pragma unroll
            for (int c4 = 0; c4 < 16; c4++) {
                ulonglong2 F0 = *(const ulonglong2*)(fp + (c4 * 4 + 0) * 64);
                ulonglong2 F1 = *(const ulonglong2*)(fp + (c4 * 4 + 1) * 64);
                ulonglong2 F2 = *(const ulonglong2*)(fp + (c4 * 4 + 2) * 64);
                ulonglong2 F3 = *(const ulonglong2*)(fp + (c4 * 4 + 3) * 64);
                #pragma unroll
                for (int i = 0; i < 8; i++) {
                    float4 w = __ldg(&w2p[i * 16 + c4]);
                    ull wx, wy, wz, ww;
                    PACK2(wx, w.x); PACK2(wy, w.y); PACK2(wz, w.z); PACK2(ww, w.w);
                    FMA2(acc[i][0], wx, F0.x, acc[i][0]); FMA2(acc[i][1], wx, F0.y, acc[i][1]);
                    FMA2(acc[i][0], wy, F1.x, acc[i][0]); FMA2(acc[i][1], wy, F1.y, acc[i][1]);
                    FMA2(acc[i][0], wz, F2.x, acc[i][0]); FMA2(acc[i][1], wz, F2.y, acc[i][1]);
                    FMA2(acc[i][0], ww, F3.x, acc[i][0]); FMA2(acc[i][1], ww, F3.y, acc[i][1]);
                }
            }
            #pragma unroll
            for (int i = 0; i < 8; i++) {
                float a0, a1, a2, a3;
                UNPACK2(a0, a1, acc[i][0]); UNPACK2(a2, a3, acc[i][1]);
                float mv = fmaxf(fmaxf(a0, a1), fmaxf(a2, a3));
                #pragma unroll
                for (int off = 1; off < 16; off <<= 1)
                    mv = fmaxf(mv, __shfl_xor_sync(0xffffffffu, mv, off));
                if ((t & 15) == 0)
                    out_points[((size_t)b * 128 + h * 64 + og * 8 + i) * S_ALL + s] = fmaxf(mv, 0.0f);
            }
        }
    }
}

extern "C" void kernel_launch(void* const* d_in, const int* in_sizes, int n_in,
                              void* d_out, int out_size) {
    const float* xyz       = (const float*)d_in[0];
    const float* points    = (const float*)d_in[1];
    const float* attention = (const float*)d_in[2];
    const float* w0 = (const float*)d_in[3];
    const float* b0 = (const float*)d_in[4];
    const float* w1 = (const float*)d_in[5];
    const float* b1 = (const float*)d_in[6];
    const float* w2 = (const float*)d_in[7];
    const float* b2 = (const float*)d_in[8];
    float* out = (float*)d_out;

    static cudaStream_t sA = nullptr, sB = nullptr, sD = nullptr;
    static cudaEvent_t eFork = nullptr, eT = nullptr, eA = nullptr, eD = nullptr;
    static cudaEvent_t eN[4] = {nullptr, nullptr, nullptr, nullptr};
    if (sA == nullptr) {
        cudaStreamCreateWithFlags(&sA, cudaStreamNonBlocking);
        cudaStreamCreateWithFlags(&sB, cudaStreamNonBlocking);
        cudaStreamCreateWithFlags(&sD, cudaStreamNonBlocking);
        cudaEventCreateWithFlags(&eFork, cudaEventDisableTiming);
        cudaEventCreateWithFlags(&eT,    cudaEventDisableTiming);
        cudaEventCreateWithFlags(&eA,    cudaEventDisableTiming);
        cudaEventCreateWithFlags(&eD,    cudaEventDisableTiming);
        for (int i = 0; i < 4; i++) cudaEventCreateWithFlags(&eN[i], cudaEventDisableTiming);
    }

    const int fps_smem = 8193 * 16 + 4097 * 4;
    cudaFuncSetAttribute(fps_kernel<0>, cudaFuncAttributeMaxDynamicSharedMemorySize, fps_smem);
    cudaFuncSetAttribute(fps_kernel<1>, cudaFuncAttributeMaxDynamicSharedMemorySize, fps_smem);

    prep_w0_kernel<<<17, 256>>>(w0);

    cudaEventRecord(eFork, 0);
    cudaStreamWaitEvent(sA, eFork, 0);
    cudaStreamWaitEvent(sB, eFork, 0);
    cudaStreamWaitEvent(sD, eFork, 0);

    // stream A: transpose -> FPS(attn) -> group(attn sites 0..127)
    transpose_kernel<<<dim3(256, 2, 8), dim3(32, 32), 0, sA>>>(points);
    cudaEventRecord(eT, sA);
    fps_kernel<0><<<BATCH, 1024, fps_smem, sA>>>(xyz, attention, out, 0, K_ATTN);
    group_mlp_kernel<0, 128><<<BATCH * 128, 128, 0, sA>>>(xyz, b0, w1, b1, w2, b2, out);
    cudaEventRecord(eA, sA);

    // stream B: FPS(none) in 4 chunks of 96 iterations
    fps_kernel<1><<<BATCH, 1024, fps_smem, sB>>>(xyz, attention, out, 0, 96);
    cudaEventRecord(eN[0], sB);
    fps_kernel<1><<<BATCH, 1024, fps_smem, sB>>>(xyz, attention, out, 96, 192);
    cudaEventRecord(eN[1], sB);
    fps_kernel<1><<<BATCH, 1024, fps_smem, sB>>>(xyz, attention, out, 192, 288);
    cudaEventRecord(eN[2], sB);
    fps_kernel<1><<<BATCH, 1024, fps_smem, sB>>>(xyz, attention, out, 288, 384);
    cudaEventRecord(eN[3], sB);

    // stream D: group(none) in 4 site-chunks, gated on FPS chunks (+transpose)
    cudaStreamWaitEvent(sD, eT, 0);
    cudaStreamWaitEvent(sD, eN[0], 0);
    group_mlp_kernel<128, 96><<<BATCH * 96, 128, 0, sD>>>(xyz, b0, w1, b1, w2, b2, out);
    cudaStreamWaitEvent(sD, eN[1], 0);
    group_mlp_kernel<224, 96><<<BATCH * 96, 128, 0, sD>>>(xyz, b0, w1, b1, w2, b2, out);
    cudaStreamWaitEvent(sD, eN[2], 0);
    group_mlp_kernel<320, 96><<<BATCH * 96, 128, 0, sD>>>(xyz, b0, w1, b1, w2, b2, out);
    cudaStreamWaitEvent(sD, eN[3], 0);
    group_mlp_kernel<416, 96><<<BATCH * 96, 128, 0, sD>>>(xyz, b0, w1, b1, w2, b2, out);
    cudaEventRecord(eD, sD);

    cudaStreamWaitEvent(0, eA, 0);
    cudaStreamWaitEvent(0, eD, 0);
}